// round 1
// baseline (speedup 1.0000x reference)
#include <cuda_runtime.h>

// Shapes (fixed by the problem): N=4, H=W=64, C_in=256, C_red=64
constexpr int HW   = 4096;
constexpr int CIN  = 256;
constexpr int CR   = 64;
constexpr int MAXN = 4;

// Scratch (device globals: allocation-free per harness rules)
__device__ float g_Wq[CIN * CR];
__device__ float g_Wk[CIN * CR];
__device__ float g_Wv[CIN * CR];
__device__ float g_Wa[CR * CIN];
__device__ float g_Q[MAXN * HW * CR];
__device__ float g_K[MAXN * HW * CR];
__device__ float g_V[MAXN * HW * CR];
__device__ float g_att[MAXN * HW * CR];   // attT[n][j][c]
__device__ float g_P[(size_t)MAXN * HW * HW];  // scores -> normalized probs (256 MiB)

// ---------------------------------------------------------------------------
// 1) Fold depthwise scale into pointwise weights: W[c][d] = dw[c] * pw[c][d]
// ---------------------------------------------------------------------------
__global__ void fold_k(const float* __restrict__ dwq, const float* __restrict__ pwq,
                       const float* __restrict__ dwk, const float* __restrict__ pwk,
                       const float* __restrict__ dwv, const float* __restrict__ pwv,
                       const float* __restrict__ dwa, const float* __restrict__ pwa) {
    int idx = blockIdx.x * 256 + threadIdx.x;
    if (idx < CIN * CR) {
        int c = idx / CR;            // for q/k/v: [CIN][CR]
        g_Wq[idx] = dwq[c] * pwq[idx];
        g_Wk[idx] = dwk[c] * pwk[idx];
        g_Wv[idx] = dwv[c] * pwv[idx];
        int cr = idx / CIN;          // for a: [CR][CIN] (same element count)
        g_Wa[idx] = dwa[cr] * pwa[idx];
    }
}

// ---------------------------------------------------------------------------
// 2) QKV projection: Q/K/V[r][d] = sum_c X[r][c] * W[c][d] + b[d]
//    32 rows per block, X tile in smem, all three outputs in one X pass.
// ---------------------------------------------------------------------------
__global__ void proj_k(const float* __restrict__ X,
                       const float* __restrict__ bq,
                       const float* __restrict__ bk,
                       const float* __restrict__ bv) {
    __shared__ float sX[32][CIN];
    const int r0  = blockIdx.x * 32;
    const int tid = threadIdx.x;

    for (int k = tid; k < 32 * CIN; k += 256)
        sX[k >> 8][k & 255] = X[(size_t)(r0 + (k >> 8)) * CIN + (k & 255)];
    __syncthreads();

    const int d  = tid & 63;
    const int rg = tid >> 6;   // 4 row-groups of 8 rows
    float aq[8], ak[8], av[8];
    const float vbq = bq[d], vbk = bk[d], vbv = bv[d];
#pragma unroll
    for (int rr = 0; rr < 8; rr++) { aq[rr] = vbq; ak[rr] = vbk; av[rr] = vbv; }

    for (int c = 0; c < CIN; c++) {
        const float wq = g_Wq[c * CR + d];
        const float wk = g_Wk[c * CR + d];
        const float wv = g_Wv[c * CR + d];
#pragma unroll
        for (int rr = 0; rr < 8; rr++) {
            const float x = sX[rg * 8 + rr][c];   // broadcast within warp
            aq[rr] = fmaf(x, wq, aq[rr]);
            ak[rr] = fmaf(x, wk, ak[rr]);
            av[rr] = fmaf(x, wv, av[rr]);
        }
    }
#pragma unroll
    for (int rr = 0; rr < 8; rr++) {
        const size_t o = (size_t)(r0 + rg * 8 + rr) * CR + d;
        g_Q[o] = aq[rr];
        g_K[o] = ak[rr];
        g_V[o] = av[rr];
    }
}

// ---------------------------------------------------------------------------
// 3) Scores: S[n][i][j] = sum_c K[n][i][c] * Q[n][j][c]
//    64x64 output tile / block; smem operands transposed [c][row] so the
//    inner loop is 2x LDS.128 + 16 FFMA per thread per k-step.
// ---------------------------------------------------------------------------
__global__ void score_k() {
    __shared__ float sKt[64][68];   // [c][i]
    __shared__ float sQt[64][68];   // [c][j]
    const int n  = blockIdx.z;
    const int i0 = blockIdx.y * 64;
    const int j0 = blockIdx.x * 64;
    const int tid = threadIdx.x;

    const float* Kp = g_K + ((size_t)n * HW + i0) * CR;
    const float* Qp = g_Q + ((size_t)n * HW + j0) * CR;
    for (int k = tid; k < 64 * 64; k += 256) {
        const int r = k >> 6, c = k & 63;
        sKt[c][r] = Kp[r * CR + c];
        sQt[c][r] = Qp[r * CR + c];
    }
    __syncthreads();

    const int tj = tid & 15, ti = tid >> 4;
    float acc[4][4] = {};
#pragma unroll 8
    for (int c = 0; c < 64; c++) {
        const float4 kv = *(const float4*)&sKt[c][ti * 4];
        const float4 qv = *(const float4*)&sQt[c][tj * 4];
        const float ka[4] = {kv.x, kv.y, kv.z, kv.w};
        const float qa[4] = {qv.x, qv.y, qv.z, qv.w};
#pragma unroll
        for (int a = 0; a < 4; a++)
#pragma unroll
            for (int b = 0; b < 4; b++)
                acc[a][b] = fmaf(ka[a], qa[b], acc[a][b]);
    }

    const size_t base = (size_t)n * HW * HW;
#pragma unroll
    for (int a = 0; a < 4; a++) {
        float4 v = make_float4(acc[a][0], acc[a][1], acc[a][2], acc[a][3]);
        *(float4*)&g_P[base + (size_t)(i0 + ti * 4 + a) * HW + (j0 + tj * 4)] = v;
    }
}

// ---------------------------------------------------------------------------
// 4) In-place row softmax over j: P[i][:] = exp(S - max)/sum
// ---------------------------------------------------------------------------
__global__ void softmax_k() {
    __shared__ float red[64];
    const size_t row = blockIdx.x;
    float4* rp = (float4*)(g_P + row * HW);
    const int tid = threadIdx.x;
    const int lane = tid & 31, wid = tid >> 5;

    float4 p[4];
#pragma unroll
    for (int t = 0; t < 4; t++) p[t] = rp[tid + 256 * t];

    float m = -3.0e38f;
#pragma unroll
    for (int t = 0; t < 4; t++)
        m = fmaxf(m, fmaxf(fmaxf(p[t].x, p[t].y), fmaxf(p[t].z, p[t].w)));
#pragma unroll
    for (int o = 16; o > 0; o >>= 1) m = fmaxf(m, __shfl_xor_sync(0xffffffffu, m, o));
    if (lane == 0) red[wid] = m;
    __syncthreads();
    if (tid == 0) {
        float mm = red[0];
        for (int w2 = 1; w2 < 8; w2++) mm = fmaxf(mm, red[w2]);
        red[32] = mm;
    }
    __syncthreads();
    m = red[32];

    float s = 0.f;
#pragma unroll
    for (int t = 0; t < 4; t++) {
        p[t].x = __expf(p[t].x - m); s += p[t].x;
        p[t].y = __expf(p[t].y - m); s += p[t].y;
        p[t].z = __expf(p[t].z - m); s += p[t].z;
        p[t].w = __expf(p[t].w - m); s += p[t].w;
    }
#pragma unroll
    for (int o = 16; o > 0; o >>= 1) s += __shfl_xor_sync(0xffffffffu, s, o);
    if (lane == 0) red[40 + wid] = s;
    __syncthreads();
    if (tid == 0) {
        float ss = 0.f;
        for (int w2 = 0; w2 < 8; w2++) ss += red[40 + w2];
        red[33] = 1.0f / ss;
    }
    __syncthreads();
    const float inv = red[33];
#pragma unroll
    for (int t = 0; t < 4; t++) {
        p[t].x *= inv; p[t].y *= inv; p[t].z *= inv; p[t].w *= inv;
        rp[tid + 256 * t] = p[t];
    }
}

// ---------------------------------------------------------------------------
// 5) attT[n][j][c] = sum_i P[n][i][j] * V[n][i][c]   (P^T @ V)
//    64j x 64c output tile per block, stream i in tiles of 64.
// ---------------------------------------------------------------------------
__global__ void pv_k() {
    __shared__ float sP[64][68];   // [i][j]
    __shared__ float sV[64][68];   // [i][c]
    const int n  = blockIdx.y;
    const int j0 = blockIdx.x * 64;
    const int tid = threadIdx.x;
    const int tc = tid & 15, tj = tid >> 4;

    const float* Pn = g_P + (size_t)n * HW * HW;
    const float* Vn = g_V + (size_t)n * HW * CR;

    float acc[4][4] = {};   // [j][c]
    for (int i0 = 0; i0 < HW; i0 += 64) {
        __syncthreads();
        for (int k = tid; k < 64 * 64; k += 256) {
            const int r = k >> 6, c = k & 63;
            sP[r][c] = Pn[(size_t)(i0 + r) * HW + j0 + c];
            sV[r][c] = Vn[(size_t)(i0 + r) * CR + c];
        }
        __syncthreads();
#pragma unroll 8
        for (int ii = 0; ii < 64; ii++) {
            const float4 pv = *(const float4*)&sP[ii][tj * 4];
            const float4 vv = *(const float4*)&sV[ii][tc * 4];
            const float pa[4] = {pv.x, pv.y, pv.z, pv.w};
            const float va[4] = {vv.x, vv.y, vv.z, vv.w};
#pragma unroll
            for (int b = 0; b < 4; b++)
#pragma unroll
                for (int a = 0; a < 4; a++)
                    acc[b][a] = fmaf(pa[b], va[a], acc[b][a]);
        }
    }
#pragma unroll
    for (int b = 0; b < 4; b++) {
        float4 v = make_float4(acc[b][0], acc[b][1], acc[b][2], acc[b][3]);
        *(float4*)&g_att[((size_t)n * HW + j0 + tj * 4 + b) * CR + tc * 4] = v;
    }
}

// ---------------------------------------------------------------------------
// 6) Raw reshape [N,Cr,HW]->[N,H,W,Cr] means att4[n,h,w,cr] = attT[n, w*64+cr, h].
//    Then y = (att4 . Wa) + ba; out = g*y + g.
// ---------------------------------------------------------------------------
__global__ void final_k(const float* __restrict__ G,
                        const float* __restrict__ ba,
                        float* __restrict__ out) {
    __shared__ float sa[64];
    const int p = blockIdx.x;          // n*HW + h*64 + w
    const int n = p >> 12;
    const int rem = p & 4095;
    const int h = rem >> 6;
    const int w = rem & 63;
    const int tid = threadIdx.x;

    if (tid < 64)
        sa[tid] = g_att[((size_t)n * HW + w * 64 + tid) * CR + h];
    __syncthreads();

    const int co = tid;
    float acc = ba[co];
#pragma unroll 8
    for (int cr = 0; cr < 64; cr++)
        acc = fmaf(sa[cr], g_Wa[cr * CIN + co], acc);

    const float g = G[(size_t)p * CIN + co];
    out[(size_t)p * CIN + co] = fmaf(g, acc, g);
}

// ---------------------------------------------------------------------------
extern "C" void kernel_launch(void* const* d_in, const int* in_sizes, int n_in,
                              void* d_out, int out_size) {
    const float* X   = (const float*)d_in[0];
    const float* G   = (const float*)d_in[1];
    const float* dwq = (const float*)d_in[2];
    const float* pwq = (const float*)d_in[3];
    const float* bq  = (const float*)d_in[4];
    const float* dwk = (const float*)d_in[5];
    const float* pwk = (const float*)d_in[6];
    const float* bk  = (const float*)d_in[7];
    const float* dwv = (const float*)d_in[8];
    const float* pwv = (const float*)d_in[9];
    const float* bv  = (const float*)d_in[10];
    const float* dwa = (const float*)d_in[11];
    const float* pwa = (const float*)d_in[12];
    const float* ba  = (const float*)d_in[13];
    float* out = (float*)d_out;

    const int N = in_sizes[0] / (HW * CIN);   // 4

    fold_k<<<(CIN * CR + 255) / 256, 256>>>(dwq, pwq, dwk, pwk, dwv, pwv, dwa, pwa);
    proj_k<<<N * (HW / 32), 256>>>(X, bq, bk, bv);
    score_k<<<dim3(HW / 64, HW / 64, N), 256>>>();
    softmax_k<<<N * HW, 256>>>();
    pv_k<<<dim3(HW / 64, N), 256>>>();
    final_k<<<N * HW, 256>>>(G, ba, out);
}

// round 4
// speedup vs baseline: 2.6986x; 2.6986x over previous
#include <cuda_runtime.h>
#include <cuda_bf16.h>
#include <stdint.h>

// Shapes fixed by the problem: N=4, H=W=64, C_in=256, C_red=64
constexpr int HW   = 4096;
constexpr int CIN  = 256;
constexpr int CR   = 64;
constexpr int MAXN = 4;

// ---------------- device scratch (allocation-free) ----------------
__device__ float g_Wq[CIN * CR];
__device__ float g_Wk[CIN * CR];
__device__ float g_Wv[CIN * CR];
__device__ float g_Wa[CR * CIN];
__device__ __nv_bfloat16 g_Qb[(size_t)MAXN * HW * CR];    // [n*HW + j][c]
__device__ __nv_bfloat16 g_Kb[(size_t)MAXN * HW * CR];    // [n*HW + i][c]
__device__ __nv_bfloat16 g_Vtb[(size_t)MAXN * CR * HW];   // [n][c][i]
__device__ float g_inv[MAXN * HW];                        // 1/rowsum_i
__device__ float g_att[(size_t)MAXN * HW * CR];           // attT[n][j][c] fp32

// ---------------- mma.sync helpers (arch-generic PTX) ----------------
__device__ __forceinline__ void mma16816(float& c0, float& c1, float& c2, float& c3,
                                         uint32_t a0, uint32_t a1, uint32_t a2, uint32_t a3,
                                         uint32_t b0, uint32_t b1) {
    asm volatile("mma.sync.aligned.m16n8k16.row.col.f32.bf16.bf16.f32 "
                 "{%0,%1,%2,%3}, {%4,%5,%6,%7}, {%8,%9}, {%0,%1,%2,%3};"
                 : "+f"(c0), "+f"(c1), "+f"(c2), "+f"(c3)
                 : "r"(a0), "r"(a1), "r"(a2), "r"(a3), "r"(b0), "r"(b1));
}
__device__ __forceinline__ uint32_t packbf2(float lo, float hi) {
    uint32_t d;
    asm("cvt.rn.bf16x2.f32 %0, %1, %2;" : "=r"(d) : "f"(hi), "f"(lo));
    return d;
}

// ---------------------------------------------------------------------------
// 1) Fold depthwise scale into pointwise weights (R1, proven)
// ---------------------------------------------------------------------------
__global__ void fold_k(const float* __restrict__ dwq, const float* __restrict__ pwq,
                       const float* __restrict__ dwk, const float* __restrict__ pwk,
                       const float* __restrict__ dwv, const float* __restrict__ pwv,
                       const float* __restrict__ dwa, const float* __restrict__ pwa) {
    int idx = blockIdx.x * 256 + threadIdx.x;
    if (idx < CIN * CR) {
        int c = idx / CR;
        g_Wq[idx] = dwq[c] * pwq[idx];
        g_Wk[idx] = dwk[c] * pwk[idx];
        g_Wv[idx] = dwv[c] * pwv[idx];
        int cr = idx / CIN;
        g_Wa[idx] = dwa[cr] * pwa[idx];
    }
}

// ---------------------------------------------------------------------------
// 2) QKV projection (R1 SIMT, proven) -> bf16 Q,K row-major; V transposed
// ---------------------------------------------------------------------------
__global__ void proj_k(const float* __restrict__ X,
                       const float* __restrict__ bq,
                       const float* __restrict__ bk,
                       const float* __restrict__ bv) {
    __shared__ float sX[32][CIN];
    const int r0  = blockIdx.x * 32;
    const int tid = threadIdx.x;

    for (int k = tid; k < 32 * CIN; k += 256)
        sX[k >> 8][k & 255] = X[(size_t)(r0 + (k >> 8)) * CIN + (k & 255)];
    __syncthreads();

    const int d  = tid & 63;
    const int rg = tid >> 6;
    float aq[8], ak[8], av[8];
    const float vbq = bq[d], vbk = bk[d], vbv = bv[d];
#pragma unroll
    for (int rr = 0; rr < 8; rr++) { aq[rr] = vbq; ak[rr] = vbk; av[rr] = vbv; }

    for (int c = 0; c < CIN; c++) {
        const float wq = g_Wq[c * CR + d];
        const float wk = g_Wk[c * CR + d];
        const float wv = g_Wv[c * CR + d];
#pragma unroll
        for (int rr = 0; rr < 8; rr++) {
            const float x = sX[rg * 8 + rr][c];
            aq[rr] = fmaf(x, wq, aq[rr]);
            ak[rr] = fmaf(x, wk, ak[rr]);
            av[rr] = fmaf(x, wv, av[rr]);
        }
    }
#pragma unroll
    for (int rr = 0; rr < 8; rr++) {
        const int r = r0 + rg * 8 + rr;
        const size_t o = (size_t)r * CR + d;
        g_Qb[o] = __float2bfloat16(aq[rr]);
        g_Kb[o] = __float2bfloat16(ak[rr]);
        const int nn = r >> 12, rl = r & 4095;
        g_Vtb[((size_t)nn * CR + d) * HW + rl] = __float2bfloat16(av[rr]);
    }
}

// ---------------------------------------------------------------------------
// 3) Pass A: 1/rowsum_i = 1/sum_j exp(K_i . Q_j). Block = (128-i tile, n).
//    A = K tile fragments in registers; B = 128-j Q chunks via smem; 32 chunks.
// ---------------------------------------------------------------------------
__global__ __launch_bounds__(256) void rowsum_k() {
    __shared__ uint32_t sQ[128 * 36];
    const int tid = threadIdx.x, lane = tid & 31, w = tid >> 5;
    const int r = lane >> 2, q = lane & 3;
    const int i0 = blockIdx.x * 128, n = blockIdx.y;

    // K-tile A-fragments: rows i0+16w+r (+8), k = c
    uint32_t a[4][4];
    const uint32_t* Kg = (const uint32_t*)g_Kb + (size_t)n * HW * 32;
#pragma unroll
    for (int ks = 0; ks < 4; ks++) {
        const uint32_t* kr = Kg + (size_t)(i0 + 16 * w + r) * 32 + ks * 8 + q;
        a[ks][0] = kr[0]; a[ks][1] = kr[256]; a[ks][2] = kr[4]; a[ks][3] = kr[260];
    }
    const uint32_t* Qg = (const uint32_t*)g_Qb + (size_t)n * HW * 32;

    float sA = 0.f, sB = 0.f;
    for (int ch = 0; ch < 32; ch++) {
        __syncthreads();
        for (int t = tid; t < 4096; t += 256)
            sQ[(t >> 5) * 36 + (t & 31)] = Qg[(size_t)(ch * 128 + (t >> 5)) * 32 + (t & 31)];
        __syncthreads();
#pragma unroll 2
        for (int nt = 0; nt < 16; nt++) {
            float c0 = 0.f, c1 = 0.f, c2 = 0.f, c3 = 0.f;
#pragma unroll
            for (int ks = 0; ks < 4; ks++) {
                const uint32_t b0 = sQ[(nt * 8 + r) * 36 + ks * 8 + q];
                const uint32_t b1 = sQ[(nt * 8 + r) * 36 + ks * 8 + q + 4];
                mma16816(c0, c1, c2, c3, a[ks][0], a[ks][1], a[ks][2], a[ks][3], b0, b1);
            }
            sA += __expf(c0) + __expf(c1);
            sB += __expf(c2) + __expf(c3);
        }
    }
    sA += __shfl_xor_sync(0xffffffffu, sA, 1);
    sA += __shfl_xor_sync(0xffffffffu, sA, 2);
    sB += __shfl_xor_sync(0xffffffffu, sB, 1);
    sB += __shfl_xor_sync(0xffffffffu, sB, 2);
    if (q == 0) {
        g_inv[n * HW + i0 + 16 * w + r]     = 1.0f / sA;
        g_inv[n * HW + i0 + 16 * w + r + 8] = 1.0f / sB;
    }
}

// ---------------------------------------------------------------------------
// 4) Pass B: attT[j,c] = sum_i exp(S[i,j]) * inv_i * V[i,c]. Block = (128-j, n).
//    64-i chunks: MMA1 S^T[j,i] -> exp*inv -> bf16 P' in smem -> MMA2 P'.Vt^T.
//    Static smem: 64x36 K + 64x36 Vt + 128x36 P + 64 inv = 37.1 KB.
// ---------------------------------------------------------------------------
__global__ __launch_bounds__(256) void attn_k() {
    __shared__ uint32_t sK[64 * 36];    // [i][c-u32]
    __shared__ uint32_t sVt[64 * 36];   // [c][i-u32]
    __shared__ uint32_t sP[128 * 36];   // [j][i-u32] bf16x2
    __shared__ float sInv[64];
    const int tid = threadIdx.x, lane = tid & 31, w = tid >> 5;
    const int r = lane >> 2, q = lane & 3;
    const int j0 = blockIdx.x * 128, n = blockIdx.y;

    // Q-tile A-fragments: rows j0+16w+r (+8), k = c
    uint32_t aq[4][4];
    const uint32_t* Qg = (const uint32_t*)g_Qb + (size_t)n * HW * 32;
#pragma unroll
    for (int ks = 0; ks < 4; ks++) {
        const uint32_t* qr = Qg + (size_t)(j0 + 16 * w + r) * 32 + ks * 8 + q;
        aq[ks][0] = qr[0]; aq[ks][1] = qr[256]; aq[ks][2] = qr[4]; aq[ks][3] = qr[260];
    }
    const uint32_t* Kg = (const uint32_t*)g_Kb + (size_t)n * HW * 32;
    const uint32_t* Vg = (const uint32_t*)g_Vtb + (size_t)n * CR * (HW / 2);
    const float* iv = g_inv + n * HW;

    float acc[8][4];
#pragma unroll
    for (int ct = 0; ct < 8; ct++)
        acc[ct][0] = acc[ct][1] = acc[ct][2] = acc[ct][3] = 0.f;

    for (int ch = 0; ch < 64; ch++) {
        const int i0 = ch * 64;
        __syncthreads();
        for (int t = tid; t < 2048; t += 256) {
            const int row = t >> 5, col = t & 31;
            sK[row * 36 + col]  = Kg[(size_t)(i0 + row) * 32 + col];
            sVt[row * 36 + col] = Vg[(size_t)row * (HW / 2) + (i0 >> 1) + col];
        }
        if (tid < 64) sInv[tid] = iv[i0 + tid];
        __syncthreads();

        // MMA1: S^T[j = 16w+r(+8)][i = nt*8+2q(+1)], then exp * inv -> P'
#pragma unroll
        for (int nt = 0; nt < 8; nt++) {
            float c0 = 0.f, c1 = 0.f, c2 = 0.f, c3 = 0.f;
#pragma unroll
            for (int ks = 0; ks < 4; ks++) {
                const uint32_t b0 = sK[(nt * 8 + r) * 36 + ks * 8 + q];
                const uint32_t b1 = sK[(nt * 8 + r) * 36 + ks * 8 + q + 4];
                mma16816(c0, c1, c2, c3, aq[ks][0], aq[ks][1], aq[ks][2], aq[ks][3], b0, b1);
            }
            const float i0v = sInv[nt * 8 + 2 * q];
            const float i1v = sInv[nt * 8 + 2 * q + 1];
            sP[(16 * w + r) * 36 + nt * 4 + q]     = packbf2(__expf(c0) * i0v, __expf(c1) * i1v);
            sP[(16 * w + r + 8) * 36 + nt * 4 + q] = packbf2(__expf(c2) * i0v, __expf(c3) * i1v);
        }
        __syncthreads();

        // MMA2: acc[j][c] += P'[j][i] . Vt[c][i]
#pragma unroll
        for (int ks2 = 0; ks2 < 4; ks2++) {
            const uint32_t a0 = sP[(16 * w + r) * 36 + ks2 * 8 + q];
            const uint32_t a1 = sP[(16 * w + r + 8) * 36 + ks2 * 8 + q];
            const uint32_t a2 = sP[(16 * w + r) * 36 + ks2 * 8 + q + 4];
            const uint32_t a3 = sP[(16 * w + r + 8) * 36 + ks2 * 8 + q + 4];
#pragma unroll
            for (int ct = 0; ct < 8; ct++) {
                const uint32_t b0 = sVt[(ct * 8 + r) * 36 + ks2 * 8 + q];
                const uint32_t b1 = sVt[(ct * 8 + r) * 36 + ks2 * 8 + q + 4];
                mma16816(acc[ct][0], acc[ct][1], acc[ct][2], acc[ct][3], a0, a1, a2, a3, b0, b1);
            }
        }
    }

    float2* A2 = (float2*)(g_att + ((size_t)n * HW + j0) * CR);
#pragma unroll
    for (int ct = 0; ct < 8; ct++) {
        A2[(size_t)(16 * w + r) * 32 + ct * 4 + q]     = make_float2(acc[ct][0], acc[ct][1]);
        A2[(size_t)(16 * w + r + 8) * 32 + ct * 4 + q] = make_float2(acc[ct][2], acc[ct][3]);
    }
}

// ---------------------------------------------------------------------------
// 5) Final (R1, proven): att4[n,h,w,cr] = attT[n, w*64+cr, h]; out = g*y+g
// ---------------------------------------------------------------------------
__global__ void final_k(const float* __restrict__ G,
                        const float* __restrict__ ba,
                        float* __restrict__ out) {
    __shared__ float sa[64];
    const int p = blockIdx.x;
    const int n = p >> 12;
    const int rem = p & 4095;
    const int h = rem >> 6;
    const int w = rem & 63;
    const int tid = threadIdx.x;

    if (tid < 64)
        sa[tid] = g_att[((size_t)n * HW + w * 64 + tid) * CR + h];
    __syncthreads();

    float acc = ba[tid];
#pragma unroll 8
    for (int cr = 0; cr < 64; cr++)
        acc = fmaf(sa[cr], g_Wa[cr * CIN + tid], acc);

    const float g = G[(size_t)p * CIN + tid];
    out[(size_t)p * CIN + tid] = fmaf(g, acc, g);
}

// ---------------------------------------------------------------------------
extern "C" void kernel_launch(void* const* d_in, const int* in_sizes, int n_in,
                              void* d_out, int out_size) {
    const float* X   = (const float*)d_in[0];
    const float* G   = (const float*)d_in[1];
    const float* dwq = (const float*)d_in[2];
    const float* pwq = (const float*)d_in[3];
    const float* bq  = (const float*)d_in[4];
    const float* dwk = (const float*)d_in[5];
    const float* pwk = (const float*)d_in[6];
    const float* bk  = (const float*)d_in[7];
    const float* dwv = (const float*)d_in[8];
    const float* pwv = (const float*)d_in[9];
    const float* bv  = (const float*)d_in[10];
    const float* dwa = (const float*)d_in[11];
    const float* pwa = (const float*)d_in[12];
    const float* ba  = (const float*)d_in[13];
    float* out = (float*)d_out;

    const int N = in_sizes[0] / (HW * CIN);   // 4

    fold_k<<<(CIN * CR + 255) / 256, 256>>>(dwq, pwq, dwk, pwk, dwv, pwv, dwa, pwa);
    proj_k<<<N * (HW / 32), 256>>>(X, bq, bk, bv);
    rowsum_k<<<dim3(HW / 128, N), 256>>>();
    attn_k<<<dim3(HW / 128, N), 256>>>();
    final_k<<<N * HW, 256>>>(G, ba, out);
}

// round 5
// speedup vs baseline: 3.4237x; 1.2687x over previous
#include <cuda_runtime.h>
#include <cuda_bf16.h>
#include <stdint.h>

// Shapes fixed by the problem: N=4, H=W=64, C_in=256, C_red=64
constexpr int HW   = 4096;
constexpr int CIN  = 256;
constexpr int CR   = 64;
constexpr int MAXN = 4;

// ---------------- device scratch (allocation-free) ----------------
__device__ float g_Wq[CIN * CR];
__device__ float g_Wk[CIN * CR];
__device__ float g_Wv[CIN * CR];
__device__ float g_Wa[CR * CIN];
__device__ __nv_bfloat16 g_Qb[(size_t)MAXN * HW * CR];    // [n*HW + j][c]
__device__ __nv_bfloat16 g_Kb[(size_t)MAXN * HW * CR];    // [n*HW + i][c]
__device__ __nv_bfloat16 g_Vtb[(size_t)MAXN * CR * HW];   // [n][c][i]
__device__ float g_part[2][MAXN * HW];                    // rowsum partials (j-halves)
__device__ float g_attp[2][(size_t)MAXN * HW * CR];       // attT partials (i-halves)

// ---------------- mma.sync helpers (arch-generic PTX) ----------------
__device__ __forceinline__ void mma16816(float& c0, float& c1, float& c2, float& c3,
                                         uint32_t a0, uint32_t a1, uint32_t a2, uint32_t a3,
                                         uint32_t b0, uint32_t b1) {
    asm volatile("mma.sync.aligned.m16n8k16.row.col.f32.bf16.bf16.f32 "
                 "{%0,%1,%2,%3}, {%4,%5,%6,%7}, {%8,%9}, {%0,%1,%2,%3};"
                 : "+f"(c0), "+f"(c1), "+f"(c2), "+f"(c3)
                 : "r"(a0), "r"(a1), "r"(a2), "r"(a3), "r"(b0), "r"(b1));
}
__device__ __forceinline__ uint32_t packbf2(float lo, float hi) {
    uint32_t d;
    asm("cvt.rn.bf16x2.f32 %0, %1, %2;" : "=r"(d) : "f"(hi), "f"(lo));
    return d;
}

// ---------------------------------------------------------------------------
// 1) Fold depthwise scale into pointwise weights (proven)
// ---------------------------------------------------------------------------
__global__ void fold_k(const float* __restrict__ dwq, const float* __restrict__ pwq,
                       const float* __restrict__ dwk, const float* __restrict__ pwk,
                       const float* __restrict__ dwv, const float* __restrict__ pwv,
                       const float* __restrict__ dwa, const float* __restrict__ pwa) {
    int idx = blockIdx.x * 256 + threadIdx.x;
    if (idx < CIN * CR) {
        int c = idx / CR;
        g_Wq[idx] = dwq[c] * pwq[idx];
        g_Wk[idx] = dwk[c] * pwk[idx];
        g_Wv[idx] = dwv[c] * pwv[idx];
        int cr = idx / CIN;
        g_Wa[idx] = dwa[cr] * pwa[idx];
    }
}

// ---------------------------------------------------------------------------
// 2) QKV projection (proven SIMT) -> bf16 Q,K row-major; V transposed
// ---------------------------------------------------------------------------
__global__ void proj_k(const float* __restrict__ X,
                       const float* __restrict__ bq,
                       const float* __restrict__ bk,
                       const float* __restrict__ bv) {
    __shared__ float sX[32][CIN];
    const int r0  = blockIdx.x * 32;
    const int tid = threadIdx.x;

    for (int k = tid; k < 32 * CIN; k += 256)
        sX[k >> 8][k & 255] = X[(size_t)(r0 + (k >> 8)) * CIN + (k & 255)];
    __syncthreads();

    const int d  = tid & 63;
    const int rg = tid >> 6;
    float aq[8], ak[8], av[8];
    const float vbq = bq[d], vbk = bk[d], vbv = bv[d];
#pragma unroll
    for (int rr = 0; rr < 8; rr++) { aq[rr] = vbq; ak[rr] = vbk; av[rr] = vbv; }

    for (int c = 0; c < CIN; c++) {
        const float wq = g_Wq[c * CR + d];
        const float wk = g_Wk[c * CR + d];
        const float wv = g_Wv[c * CR + d];
#pragma unroll
        for (int rr = 0; rr < 8; rr++) {
            const float x = sX[rg * 8 + rr][c];
            aq[rr] = fmaf(x, wq, aq[rr]);
            ak[rr] = fmaf(x, wk, ak[rr]);
            av[rr] = fmaf(x, wv, av[rr]);
        }
    }
#pragma unroll
    for (int rr = 0; rr < 8; rr++) {
        const int r = r0 + rg * 8 + rr;
        const size_t o = (size_t)r * CR + d;
        g_Qb[o] = __float2bfloat16(aq[rr]);
        g_Kb[o] = __float2bfloat16(ak[rr]);
        const int nn = r >> 12, rl = r & 4095;
        g_Vtb[((size_t)nn * CR + d) * HW + rl] = __float2bfloat16(av[rr]);
    }
}

// ---------------------------------------------------------------------------
// 3) Pass A: rowsum partials over a j-half. Block = (128-i tile, j-half, n).
// ---------------------------------------------------------------------------
__global__ __launch_bounds__(256) void rowsum_k() {
    __shared__ uint32_t sQ[128 * 36];
    const int tid = threadIdx.x, lane = tid & 31, w = tid >> 5;
    const int r = lane >> 2, q = lane & 3;
    const int i0 = blockIdx.x * 128, jh = blockIdx.y, n = blockIdx.z;

    uint32_t a[4][4];
    const uint32_t* Kg = (const uint32_t*)g_Kb + (size_t)n * HW * 32;
#pragma unroll
    for (int ks = 0; ks < 4; ks++) {
        const uint32_t* kr = Kg + (size_t)(i0 + 16 * w + r) * 32 + ks * 8 + q;
        a[ks][0] = kr[0]; a[ks][1] = kr[256]; a[ks][2] = kr[4]; a[ks][3] = kr[260];
    }
    const uint32_t* Qg = (const uint32_t*)g_Qb + ((size_t)n * HW + jh * 2048) * 32;

    float sA = 0.f, sB = 0.f;
    for (int ch = 0; ch < 16; ch++) {
        __syncthreads();
        for (int t = tid; t < 4096; t += 256)
            sQ[(t >> 5) * 36 + (t & 31)] = Qg[(size_t)(ch * 128 + (t >> 5)) * 32 + (t & 31)];
        __syncthreads();
#pragma unroll 2
        for (int nt = 0; nt < 16; nt++) {
            float c0 = 0.f, c1 = 0.f, c2 = 0.f, c3 = 0.f;
#pragma unroll
            for (int ks = 0; ks < 4; ks++) {
                const uint32_t b0 = sQ[(nt * 8 + r) * 36 + ks * 8 + q];
                const uint32_t b1 = sQ[(nt * 8 + r) * 36 + ks * 8 + q + 4];
                mma16816(c0, c1, c2, c3, a[ks][0], a[ks][1], a[ks][2], a[ks][3], b0, b1);
            }
            sA += __expf(c0) + __expf(c1);
            sB += __expf(c2) + __expf(c3);
        }
    }
    sA += __shfl_xor_sync(0xffffffffu, sA, 1);
    sA += __shfl_xor_sync(0xffffffffu, sA, 2);
    sB += __shfl_xor_sync(0xffffffffu, sB, 1);
    sB += __shfl_xor_sync(0xffffffffu, sB, 2);
    if (q == 0) {
        g_part[jh][n * HW + i0 + 16 * w + r]     = sA;
        g_part[jh][n * HW + i0 + 16 * w + r + 8] = sB;
    }
}

// ---------------------------------------------------------------------------
// 4) Pass B over an i-half: attp[ih][j,c] = sum_{i in half} exp(S)*inv_i*V[i,c]
//    Block = (128-j tile, i-half, n). P' fragments built IN REGISTERS from
//    MMA1 C-fragments (layouts validated in R4) -- no smem round-trip.
// ---------------------------------------------------------------------------
__global__ __launch_bounds__(256) void attn_k() {
    __shared__ uint32_t sK[64 * 36];    // [i][c-u32]
    __shared__ uint32_t sVt[64 * 36];   // [c][i-u32]
    __shared__ float sInv[64];
    const int tid = threadIdx.x, lane = tid & 31, w = tid >> 5;
    const int r = lane >> 2, q = lane & 3;
    const int j0 = blockIdx.x * 128, ih = blockIdx.y, n = blockIdx.z;

    uint32_t aq[4][4];
    const uint32_t* Qg = (const uint32_t*)g_Qb + (size_t)n * HW * 32;
#pragma unroll
    for (int ks = 0; ks < 4; ks++) {
        const uint32_t* qr = Qg + (size_t)(j0 + 16 * w + r) * 32 + ks * 8 + q;
        aq[ks][0] = qr[0]; aq[ks][1] = qr[256]; aq[ks][2] = qr[4]; aq[ks][3] = qr[260];
    }
    const uint32_t* Kg = (const uint32_t*)g_Kb + (size_t)n * HW * 32;
    const uint32_t* Vg = (const uint32_t*)g_Vtb + (size_t)n * CR * (HW / 2);
    const float* p0 = g_part[0] + n * HW;
    const float* p1 = g_part[1] + n * HW;

    float acc[8][4];
#pragma unroll
    for (int ct = 0; ct < 8; ct++)
        acc[ct][0] = acc[ct][1] = acc[ct][2] = acc[ct][3] = 0.f;

    for (int ch = 0; ch < 32; ch++) {
        const int i0 = ih * 2048 + ch * 64;
        __syncthreads();
        for (int t = tid; t < 2048; t += 256) {
            const int row = t >> 5, col = t & 31;
            sK[row * 36 + col]  = Kg[(size_t)(i0 + row) * 32 + col];
            sVt[row * 36 + col] = Vg[(size_t)row * (HW / 2) + (i0 >> 1) + col];
        }
        if (tid < 64) sInv[tid] = 1.0f / (p0[i0 + tid] + p1[i0 + tid]);
        __syncthreads();

#pragma unroll
        for (int ks2 = 0; ks2 < 4; ks2++) {
            uint32_t ap[4];
#pragma unroll
            for (int half = 0; half < 2; half++) {
                const int nt = 2 * ks2 + half;
                float c0 = 0.f, c1 = 0.f, c2 = 0.f, c3 = 0.f;
#pragma unroll
                for (int ks = 0; ks < 4; ks++) {
                    const uint32_t b0 = sK[(nt * 8 + r) * 36 + ks * 8 + q];
                    const uint32_t b1 = sK[(nt * 8 + r) * 36 + ks * 8 + q + 4];
                    mma16816(c0, c1, c2, c3, aq[ks][0], aq[ks][1], aq[ks][2], aq[ks][3], b0, b1);
                }
                const float i0v = sInv[nt * 8 + 2 * q];
                const float i1v = sInv[nt * 8 + 2 * q + 1];
                ap[half]     = packbf2(__expf(c0) * i0v, __expf(c1) * i1v);
                ap[2 + half] = packbf2(__expf(c2) * i0v, __expf(c3) * i1v);
            }
            // ap[0]=a0(nt=2ks2 rows r), ap[2]=a1(nt=2ks2 rows r+8),
            // ap[1]=a2(nt=2ks2+1 rows r), ap[3]=a3(nt=2ks2+1 rows r+8)
#pragma unroll
            for (int ct = 0; ct < 8; ct++) {
                const uint32_t b0 = sVt[(ct * 8 + r) * 36 + ks2 * 8 + q];
                const uint32_t b1 = sVt[(ct * 8 + r) * 36 + ks2 * 8 + q + 4];
                mma16816(acc[ct][0], acc[ct][1], acc[ct][2], acc[ct][3],
                         ap[0], ap[2], ap[1], ap[3], b0, b1);
            }
        }
    }

    float2* A2 = (float2*)(g_attp[ih] + ((size_t)n * HW + j0) * CR);
#pragma unroll
    for (int ct = 0; ct < 8; ct++) {
        A2[(size_t)(16 * w + r) * 32 + ct * 4 + q]     = make_float2(acc[ct][0], acc[ct][1]);
        A2[(size_t)(16 * w + r + 8) * 32 + ct * 4 + q] = make_float2(acc[ct][2], acc[ct][3]);
    }
}

// ---------------------------------------------------------------------------
// 5) Final: att4[n,h,w,cr] = attT[n, w*64+cr, h]; y = att4.Wa + ba; out = g*y+g
// ---------------------------------------------------------------------------
__global__ void final_k(const float* __restrict__ G,
                        const float* __restrict__ ba,
                        float* __restrict__ out) {
    __shared__ float sa[64];
    const int p = blockIdx.x;
    const int n = p >> 12;
    const int rem = p & 4095;
    const int h = rem >> 6;
    const int w = rem & 63;
    const int tid = threadIdx.x;

    if (tid < 64) {
        const size_t idx = ((size_t)n * HW + w * 64 + tid) * CR + h;
        sa[tid] = g_attp[0][idx] + g_attp[1][idx];
    }
    __syncthreads();

    float acc = ba[tid];
#pragma unroll 8
    for (int cr = 0; cr < 64; cr++)
        acc = fmaf(sa[cr], g_Wa[cr * CIN + tid], acc);

    const float g = G[(size_t)p * CIN + tid];
    out[(size_t)p * CIN + tid] = fmaf(g, acc, g);
}

// ---------------------------------------------------------------------------
extern "C" void kernel_launch(void* const* d_in, const int* in_sizes, int n_in,
                              void* d_out, int out_size) {
    const float* X   = (const float*)d_in[0];
    const float* G   = (const float*)d_in[1];
    const float* dwq = (const float*)d_in[2];
    const float* pwq = (const float*)d_in[3];
    const float* bq  = (const float*)d_in[4];
    const float* dwk = (const float*)d_in[5];
    const float* pwk = (const float*)d_in[6];
    const float* bk  = (const float*)d_in[7];
    const float* dwv = (const float*)d_in[8];
    const float* pwv = (const float*)d_in[9];
    const float* bv  = (const float*)d_in[10];
    const float* dwa = (const float*)d_in[11];
    const float* pwa = (const float*)d_in[12];
    const float* ba  = (const float*)d_in[13];
    float* out = (float*)d_out;

    const int N = in_sizes[0] / (HW * CIN);   // 4

    fold_k<<<(CIN * CR + 255) / 256, 256>>>(dwq, pwq, dwk, pwk, dwv, pwv, dwa, pwa);
    proj_k<<<N * (HW / 32), 256>>>(X, bq, bk, bv);
    rowsum_k<<<dim3(HW / 128, 2, N), 256>>>();
    attn_k<<<dim3(HW / 128, 2, N), 256>>>();
    final_k<<<N * HW, 256>>>(G, ba, out);
}

// round 6
// speedup vs baseline: 5.6131x; 1.6395x over previous
#include <cuda_runtime.h>
#include <cuda_bf16.h>
#include <stdint.h>

// Shapes fixed by the problem: N=4, H=W=64, C_in=256, C_red=64
constexpr int HW   = 4096;
constexpr int CIN  = 256;
constexpr int CR   = 64;
constexpr int MAXN = 4;

// ---------------- device scratch (allocation-free) ----------------
__device__ float g_Wa[CR * CIN];                          // fp32 [cr][cout]
__device__ uint32_t g_Wfrag[2 * 12288];                   // qkv weights in B-fragment order
__device__ float g_b192[192];
__device__ __nv_bfloat16 g_Qb[(size_t)MAXN * HW * CR];    // [n*HW + j][c]
__device__ __nv_bfloat16 g_Kb[(size_t)MAXN * HW * CR];    // [n*HW + i][c]
__device__ __nv_bfloat16 g_Vtb[(size_t)MAXN * CR * HW];   // [n][c][i]
__device__ float g_part[4][MAXN * HW];                    // rowsum partials (j-quarters)
__device__ float g_inv[MAXN * HW];                        // 1/rowsum
__device__ float g_attp[2][(size_t)MAXN * CR * HW];       // att partials [ih][n][c][j]

// ---------------- helpers ----------------
__device__ __forceinline__ uint32_t s2u(const void* p) {
    return (uint32_t)__cvta_generic_to_shared(p);
}
__device__ __forceinline__ void mma16816(float& c0, float& c1, float& c2, float& c3,
                                         uint32_t a0, uint32_t a1, uint32_t a2, uint32_t a3,
                                         uint32_t b0, uint32_t b1) {
    asm volatile("mma.sync.aligned.m16n8k16.row.col.f32.bf16.bf16.f32 "
                 "{%0,%1,%2,%3}, {%4,%5,%6,%7}, {%8,%9}, {%0,%1,%2,%3};"
                 : "+f"(c0), "+f"(c1), "+f"(c2), "+f"(c3)
                 : "r"(a0), "r"(a1), "r"(a2), "r"(a3), "r"(b0), "r"(b1));
}
__device__ __forceinline__ uint32_t packbf2(float lo, float hi) {
    uint32_t d;
    asm("cvt.rn.bf16x2.f32 %0, %1, %2;" : "=r"(d) : "f"(hi), "f"(lo));
    return d;
}
__device__ __forceinline__ void cpasync16(uint32_t saddr, const void* g) {
    asm volatile("cp.async.ca.shared.global [%0], [%1], 16;" :: "r"(saddr), "l"(g));
}
__device__ __forceinline__ void cpcommit() { asm volatile("cp.async.commit_group;"); }
template<int N> __device__ __forceinline__ void cpwait() {
    asm volatile("cp.async.wait_group %0;" :: "n"(N));
}
__device__ __forceinline__ void ldsm_x4(uint32_t& r0, uint32_t& r1, uint32_t& r2, uint32_t& r3,
                                        uint32_t addr) {
    asm volatile("ldmatrix.sync.aligned.m8n8.x4.shared.b16 {%0,%1,%2,%3}, [%4];"
                 : "=r"(r0), "=r"(r1), "=r"(r2), "=r"(r3) : "r"(addr));
}

// ---------------------------------------------------------------------------
// 1) fold: build Wa (fp32), combined bias, and qkv weights in B-frag order.
//    WT[n][c] = dw[c]*pw[c][d]; frag slot for (n,c-pair) per mma.sync B layout.
// ---------------------------------------------------------------------------
__global__ void fold_k(const float* __restrict__ dwq, const float* __restrict__ pwq,
                       const float* __restrict__ bq,
                       const float* __restrict__ dwk, const float* __restrict__ pwk,
                       const float* __restrict__ bk,
                       const float* __restrict__ dwv, const float* __restrict__ pwv,
                       const float* __restrict__ bv,
                       const float* __restrict__ dwa, const float* __restrict__ pwa) {
    const int idx = blockIdx.x * 256 + threadIdx.x;   // 0..24575
    if (idx < 16384) {
        const int cr = idx >> 8;
        g_Wa[idx] = dwa[cr] * pwa[idx];
    }
    if (idx < 192)
        g_b192[idx] = (idx < 64) ? bq[idx] : (idx < 128 ? bk[idx - 64] : bv[idx - 128]);

    const int nn = idx >> 7;       // output unit 0..191
    const int p  = idx & 127;      // c-pair 0..127
    const int c0 = 2 * p, c1 = 2 * p + 1;
    float w0, w1;
    if (nn < 64)       { w0 = dwq[c0] * pwq[c0 * 64 + nn];        w1 = dwq[c1] * pwq[c1 * 64 + nn]; }
    else if (nn < 128) { const int m = nn - 64;  w0 = dwk[c0] * pwk[c0 * 64 + m]; w1 = dwk[c1] * pwk[c1 * 64 + m]; }
    else               { const int m = nn - 128; w0 = dwv[c0] * pwv[c0 * 64 + m]; w1 = dwv[c1] * pwv[c1 * 64 + m]; }
    const int h = nn / 96, nl = nn % 96, nt = nl >> 3, r = nl & 7;
    const int ks = p >> 3, rem = p & 7, q = rem & 3, slot = rem >> 2;
    g_Wfrag[(((h * 12 + nt) * 16 + ks) * 32 + r * 4 + q) * 2 + slot] = packbf2(w0, w1);
}

// ---------------------------------------------------------------------------
// 2) QKV projection via mma.sync: Y[16384,192] = X.WT^T + b. Block = 128 m-rows
//    x 96 n (half). Weights pre-swizzled in smem; A-frags from global + pack.
// ---------------------------------------------------------------------------
__global__ __launch_bounds__(256) void proj_k(const float* __restrict__ X) {
    __shared__ uint32_t sW[12288];   // 48 KB
    const int tid = threadIdx.x, lane = tid & 31, w = tid >> 5;
    const int r = lane >> 2, q = lane & 3;
    const int m0 = blockIdx.x * 128, h = blockIdx.y;

    const uint32_t swb = s2u(sW);
    const uint32_t* Wsrc = g_Wfrag + h * 12288;
    for (int t = tid; t < 3072; t += 256) cpasync16(swb + t * 16, Wsrc + t * 4);
    cpcommit(); cpwait<0>(); __syncthreads();

    float acc[12][4];
#pragma unroll
    for (int nt = 0; nt < 12; nt++) {
        const int n0 = h * 96 + nt * 8 + 2 * q;
        const float b0 = g_b192[n0], b1 = g_b192[n0 + 1];
        acc[nt][0] = b0; acc[nt][1] = b1; acc[nt][2] = b0; acc[nt][3] = b1;
    }

    const int mA = m0 + 16 * w + r;
    const float2* X2 = (const float2*)X;
    const uint2* sW2 = (const uint2*)sW;
#pragma unroll 4
    for (int ks = 0; ks < 16; ks++) {
        const float2 u0 = X2[(size_t)mA * 128 + ks * 8 + q];
        const float2 u1 = X2[(size_t)(mA + 8) * 128 + ks * 8 + q];
        const float2 u2 = X2[(size_t)mA * 128 + ks * 8 + q + 4];
        const float2 u3 = X2[(size_t)(mA + 8) * 128 + ks * 8 + q + 4];
        const uint32_t a0 = packbf2(u0.x, u0.y);
        const uint32_t a1 = packbf2(u1.x, u1.y);
        const uint32_t a2 = packbf2(u2.x, u2.y);
        const uint32_t a3 = packbf2(u3.x, u3.y);
#pragma unroll
        for (int nt = 0; nt < 12; nt++) {
            const uint2 b = sW2[(nt * 16 + ks) * 32 + lane];
            mma16816(acc[nt][0], acc[nt][1], acc[nt][2], acc[nt][3], a0, a1, a2, a3, b.x, b.y);
        }
    }

    uint32_t* Qw = (uint32_t*)g_Qb;
    uint32_t* Kw = (uint32_t*)g_Kb;
    const int nb = mA >> 12, ii = mA & 4095;
#pragma unroll
    for (int nt = 0; nt < 12; nt++) {
        const int n0 = h * 96 + nt * 8 + 2 * q;
        if (n0 < 64) {
            Qw[(size_t)mA * 32 + (n0 >> 1)]       = packbf2(acc[nt][0], acc[nt][1]);
            Qw[(size_t)(mA + 8) * 32 + (n0 >> 1)] = packbf2(acc[nt][2], acc[nt][3]);
        } else if (n0 < 128) {
            const int k0 = n0 - 64;
            Kw[(size_t)mA * 32 + (k0 >> 1)]       = packbf2(acc[nt][0], acc[nt][1]);
            Kw[(size_t)(mA + 8) * 32 + (k0 >> 1)] = packbf2(acc[nt][2], acc[nt][3]);
        } else {
            const int c = n0 - 128;
            g_Vtb[((size_t)nb * 64 + c) * HW + ii]          = __float2bfloat16(acc[nt][0]);
            g_Vtb[((size_t)nb * 64 + c + 1) * HW + ii]      = __float2bfloat16(acc[nt][1]);
            g_Vtb[((size_t)nb * 64 + c) * HW + ii + 8]      = __float2bfloat16(acc[nt][2]);
            g_Vtb[((size_t)nb * 64 + c + 1) * HW + ii + 8]  = __float2bfloat16(acc[nt][3]);
        }
    }
}

// ---------------------------------------------------------------------------
// 3) Pass A: rowsum partials over a j-quarter. Block = (64-i tile, jq, n),
//    128 threads, cp.async double-buffered 128-j chunks, ldmatrix B-frags.
// ---------------------------------------------------------------------------
__global__ __launch_bounds__(128) void rowsum_k() {
    __shared__ uint32_t sQ[2][128 * 36];
    const int tid = threadIdx.x, lane = tid & 31, w = tid >> 5;
    const int r = lane >> 2, q = lane & 3;
    const int i0 = blockIdx.x * 64, jq = blockIdx.y, n = blockIdx.z;

    uint32_t a[4][4];
    const uint32_t* Kg = (const uint32_t*)g_Kb + (size_t)n * HW * 32;
#pragma unroll
    for (int ks = 0; ks < 4; ks++) {
        const uint32_t* kr = Kg + (size_t)(i0 + 16 * w + r) * 32 + ks * 8 + q;
        a[ks][0] = kr[0]; a[ks][1] = kr[256]; a[ks][2] = kr[4]; a[ks][3] = kr[260];
    }
    const uint32_t* Qg = (const uint32_t*)g_Qb + ((size_t)n * HW + jq * 1024) * 32;
    const uint32_t sqb0 = s2u(sQ[0]), sqb1 = s2u(sQ[1]);
    const uint32_t loff = (lane & 7) * 144 + (lane >> 3) * 16;

    auto issue = [&](int ch, uint32_t base) {
#pragma unroll
        for (int t = tid; t < 1024; t += 128) {
            const int row = t >> 3, c4 = (t & 7) * 4;
            cpasync16(base + row * 144 + c4 * 4, Qg + (size_t)(ch * 128 + row) * 32 + c4);
        }
    };
    issue(0, sqb0); cpcommit();

    float sA = 0.f, sB = 0.f;
    for (int ch = 0; ch < 8; ch++) {
        if (ch < 7) { issue(ch + 1, (ch & 1) ? sqb0 : sqb1); cpcommit(); cpwait<1>(); }
        else cpwait<0>();
        __syncthreads();
        const uint32_t base = (ch & 1) ? sqb1 : sqb0;
#pragma unroll 4
        for (int nt = 0; nt < 16; nt++) {
            uint32_t b00, b10, b01, b11, b02, b12, b03, b13;
            ldsm_x4(b00, b10, b01, b11, base + nt * 1152 + loff);
            ldsm_x4(b02, b12, b03, b13, base + nt * 1152 + 64 + loff);
            float c0 = 0.f, c1 = 0.f, c2 = 0.f, c3 = 0.f;
            mma16816(c0, c1, c2, c3, a[0][0], a[0][1], a[0][2], a[0][3], b00, b10);
            mma16816(c0, c1, c2, c3, a[1][0], a[1][1], a[1][2], a[1][3], b01, b11);
            mma16816(c0, c1, c2, c3, a[2][0], a[2][1], a[2][2], a[2][3], b02, b12);
            mma16816(c0, c1, c2, c3, a[3][0], a[3][1], a[3][2], a[3][3], b03, b13);
            sA += __expf(c0) + __expf(c1);
            sB += __expf(c2) + __expf(c3);
        }
        __syncthreads();
    }
    sA += __shfl_xor_sync(0xffffffffu, sA, 1);
    sA += __shfl_xor_sync(0xffffffffu, sA, 2);
    sB += __shfl_xor_sync(0xffffffffu, sB, 1);
    sB += __shfl_xor_sync(0xffffffffu, sB, 2);
    if (q == 0) {
        g_part[jq][n * HW + i0 + 16 * w + r]     = sA;
        g_part[jq][n * HW + i0 + 16 * w + r + 8] = sB;
    }
}

// ---------------------------------------------------------------------------
// 3b) combine partials -> 1/rowsum
// ---------------------------------------------------------------------------
__global__ void inv_k() {
    const int i = blockIdx.x * 256 + threadIdx.x;
    g_inv[i] = 1.0f / (g_part[0][i] + g_part[1][i] + g_part[2][i] + g_part[3][i]);
}

// ---------------------------------------------------------------------------
// 4) Pass B over i-half: att[c][j] += exp(S)*inv_i*V. Block = (64-j, ih, n),
//    128 threads, cp.async double-buffered 64-i chunks, ldmatrix B-frags,
//    P' fragments built in registers (proven R5 mapping).
// ---------------------------------------------------------------------------
__global__ __launch_bounds__(128) void attn_k() {
    __shared__ uint32_t sK[2][64 * 36];
    __shared__ uint32_t sVt[2][64 * 36];
    __shared__ float sInv[2][64];
    const int tid = threadIdx.x, lane = tid & 31, w = tid >> 5;
    const int r = lane >> 2, q = lane & 3;
    const int j0 = blockIdx.x * 64, ih = blockIdx.y, n = blockIdx.z;

    uint32_t aq[4][4];
    const uint32_t* Qg = (const uint32_t*)g_Qb + (size_t)n * HW * 32;
#pragma unroll
    for (int ks = 0; ks < 4; ks++) {
        const uint32_t* qr = Qg + (size_t)(j0 + 16 * w + r) * 32 + ks * 8 + q;
        aq[ks][0] = qr[0]; aq[ks][1] = qr[256]; aq[ks][2] = qr[4]; aq[ks][3] = qr[260];
    }
    const uint32_t* Kg = (const uint32_t*)g_Kb + (size_t)n * HW * 32;
    const uint32_t* Vg = (const uint32_t*)g_Vtb + (size_t)n * CR * (HW / 2);
    const float* invp = g_inv + n * HW;

    const uint32_t skb[2] = {s2u(sK[0]),  s2u(sK[1])};
    const uint32_t svb[2] = {s2u(sVt[0]), s2u(sVt[1])};
    const uint32_t sib[2] = {s2u(sInv[0]), s2u(sInv[1])};
    const uint32_t loff1 = (lane & 7) * 144 + (lane >> 3) * 16;
    const uint32_t loff2 = (lane & 7) * 144 + ((lane >> 3) & 1) * 16 + (lane >> 4) * 1152;

    auto issue = [&](int ch, int buf) {
        const int i0 = ih * 2048 + ch * 64;
#pragma unroll
        for (int t = tid; t < 512; t += 128) {
            const int row = t >> 3, c4 = (t & 7) * 4;
            cpasync16(skb[buf] + row * 144 + c4 * 4, Kg + (size_t)(i0 + row) * 32 + c4);
            cpasync16(svb[buf] + row * 144 + c4 * 4, Vg + (size_t)row * 2048 + (i0 >> 1) + c4);
        }
        if (tid < 16) cpasync16(sib[buf] + tid * 16, invp + i0 + tid * 4);
    };

    float acc[8][4];
#pragma unroll
    for (int ct = 0; ct < 8; ct++)
        acc[ct][0] = acc[ct][1] = acc[ct][2] = acc[ct][3] = 0.f;

    issue(0, 0); cpcommit();
    for (int ch = 0; ch < 32; ch++) {
        if (ch < 31) { issue(ch + 1, (ch + 1) & 1); cpcommit(); cpwait<1>(); }
        else cpwait<0>();
        __syncthreads();
        const int buf = ch & 1;
        const uint32_t kb = skb[buf], vb = svb[buf];
        const float* iv = sInv[buf];

#pragma unroll
        for (int ks2 = 0; ks2 < 4; ks2++) {
            uint32_t ap[4];
#pragma unroll
            for (int half = 0; half < 2; half++) {
                const int nt = 2 * ks2 + half;
                uint32_t b00, b10, b01, b11, b02, b12, b03, b13;
                ldsm_x4(b00, b10, b01, b11, kb + nt * 1152 + loff1);
                ldsm_x4(b02, b12, b03, b13, kb + nt * 1152 + 64 + loff1);
                float c0 = 0.f, c1 = 0.f, c2 = 0.f, c3 = 0.f;
                mma16816(c0, c1, c2, c3, aq[0][0], aq[0][1], aq[0][2], aq[0][3], b00, b10);
                mma16816(c0, c1, c2, c3, aq[1][0], aq[1][1], aq[1][2], aq[1][3], b01, b11);
                mma16816(c0, c1, c2, c3, aq[2][0], aq[2][1], aq[2][2], aq[2][3], b02, b12);
                mma16816(c0, c1, c2, c3, aq[3][0], aq[3][1], aq[3][2], aq[3][3], b03, b13);
                const float i0v = iv[nt * 8 + 2 * q];
                const float i1v = iv[nt * 8 + 2 * q + 1];
                ap[half]     = packbf2(__expf(c0) * i0v, __expf(c1) * i1v);
                ap[2 + half] = packbf2(__expf(c2) * i0v, __expf(c3) * i1v);
            }
#pragma unroll
            for (int ctp = 0; ctp < 4; ctp++) {
                uint32_t v0, v1, v2, v3;
                ldsm_x4(v0, v1, v2, v3, vb + ctp * 2304 + ks2 * 32 + loff2);
                mma16816(acc[2 * ctp][0], acc[2 * ctp][1], acc[2 * ctp][2], acc[2 * ctp][3],
                         ap[0], ap[2], ap[1], ap[3], v0, v1);
                mma16816(acc[2 * ctp + 1][0], acc[2 * ctp + 1][1], acc[2 * ctp + 1][2], acc[2 * ctp + 1][3],
                         ap[0], ap[2], ap[1], ap[3], v2, v3);
            }
        }
        __syncthreads();
    }

    // epilogue: write [n][c][j] partial
    float* A = g_attp[ih] + (size_t)n * CR * HW;
    const int jrow = j0 + 16 * w + r;
#pragma unroll
    for (int ct = 0; ct < 8; ct++) {
        const int c = ct * 8 + 2 * q;
        A[(size_t)c * HW + jrow]           = acc[ct][0];
        A[(size_t)(c + 1) * HW + jrow]     = acc[ct][1];
        A[(size_t)c * HW + jrow + 8]       = acc[ct][2];
        A[(size_t)(c + 1) * HW + jrow + 8] = acc[ct][3];
    }
}

// ---------------------------------------------------------------------------
// 5) Final: att4[n,h,w,cr] = att[c=h][j=w*64+cr]; y = att4.Wa + ba; out = g*y+g
// ---------------------------------------------------------------------------
__global__ void final_k(const float* __restrict__ G,
                        const float* __restrict__ ba,
                        float* __restrict__ out) {
    __shared__ float sa[64];
    const int p = blockIdx.x;
    const int n = p >> 12;
    const int rem = p & 4095;
    const int h = rem >> 6;
    const int w = rem & 63;
    const int tid = threadIdx.x;

    if (tid < 64) {
        const size_t base = ((size_t)n * CR + h) * HW + w * 64 + tid;
        sa[tid] = g_attp[0][base] + g_attp[1][base];
    }
    __syncthreads();

    float acc = ba[tid];
#pragma unroll 8
    for (int cr = 0; cr < 64; cr++)
        acc = fmaf(sa[cr], g_Wa[cr * CIN + tid], acc);

    const float g = G[(size_t)p * CIN + tid];
    out[(size_t)p * CIN + tid] = fmaf(g, acc, g);
}

// ---------------------------------------------------------------------------
extern "C" void kernel_launch(void* const* d_in, const int* in_sizes, int n_in,
                              void* d_out, int out_size) {
    const float* X   = (const float*)d_in[0];
    const float* G   = (const float*)d_in[1];
    const float* dwq = (const float*)d_in[2];
    const float* pwq = (const float*)d_in[3];
    const float* bq  = (const float*)d_in[4];
    const float* dwk = (const float*)d_in[5];
    const float* pwk = (const float*)d_in[6];
    const float* bk  = (const float*)d_in[7];
    const float* dwv = (const float*)d_in[8];
    const float* pwv = (const float*)d_in[9];
    const float* bv  = (const float*)d_in[10];
    const float* dwa = (const float*)d_in[11];
    const float* pwa = (const float*)d_in[12];
    const float* ba  = (const float*)d_in[13];
    float* out = (float*)d_out;

    const int N = in_sizes[0] / (HW * CIN);   // 4

    fold_k<<<96, 256>>>(dwq, pwq, bq, dwk, pwk, bk, dwv, pwv, bv, dwa, pwa);
    proj_k<<<dim3((N * HW) / 128, 2), 256>>>(X);
    rowsum_k<<<dim3(HW / 64, 4, N), 128>>>();
    inv_k<<<(N * HW) / 256, 256>>>();
    attn_k<<<dim3(HW / 64, 2, N), 128>>>();
    final_k<<<N * HW, 256>>>(G, ba, out);
}

// round 7
// speedup vs baseline: 6.5465x; 1.1663x over previous
#include <cuda_runtime.h>
#include <cuda_bf16.h>
#include <stdint.h>

// Shapes fixed by the problem: N=4, H=W=64, C_in=256, C_red=64
constexpr int HW   = 4096;
constexpr int CIN  = 256;
constexpr int CR   = 64;
constexpr int MAXN = 4;

// ---------------- device scratch (allocation-free) ----------------
__device__ float g_Wa[CR * CIN];                          // fp32 [cr][cout]
__device__ uint32_t g_Wfrag[2 * 12288];                   // qkv weights in B-fragment order
__device__ float g_b192[192];
__device__ __nv_bfloat16 g_Qb[(size_t)MAXN * HW * CR];    // [n*HW + j][c]
__device__ __nv_bfloat16 g_Kb[(size_t)MAXN * HW * CR];    // [n*HW + i][c]
__device__ __nv_bfloat16 g_Vtb[(size_t)MAXN * CR * HW];   // [n][c][i]
__device__ float g_part[4][MAXN * HW];                    // rowsum partials (j-quarters)
__device__ float g_attp[4][(size_t)MAXN * CR * HW];       // att partials [ih][n][c][j]

// ---------------- helpers ----------------
__device__ __forceinline__ uint32_t s2u(const void* p) {
    return (uint32_t)__cvta_generic_to_shared(p);
}
__device__ __forceinline__ void mma16816(float& c0, float& c1, float& c2, float& c3,
                                         uint32_t a0, uint32_t a1, uint32_t a2, uint32_t a3,
                                         uint32_t b0, uint32_t b1) {
    asm volatile("mma.sync.aligned.m16n8k16.row.col.f32.bf16.bf16.f32 "
                 "{%0,%1,%2,%3}, {%4,%5,%6,%7}, {%8,%9}, {%0,%1,%2,%3};"
                 : "+f"(c0), "+f"(c1), "+f"(c2), "+f"(c3)
                 : "r"(a0), "r"(a1), "r"(a2), "r"(a3), "r"(b0), "r"(b1));
}
__device__ __forceinline__ uint32_t packbf2(float lo, float hi) {
    uint32_t d;
    asm("cvt.rn.bf16x2.f32 %0, %1, %2;" : "=r"(d) : "f"(hi), "f"(lo));
    return d;
}
__device__ __forceinline__ void cpasync16(uint32_t saddr, const void* g) {
    asm volatile("cp.async.ca.shared.global [%0], [%1], 16;" :: "r"(saddr), "l"(g));
}
__device__ __forceinline__ void cpcommit() { asm volatile("cp.async.commit_group;"); }
template<int N> __device__ __forceinline__ void cpwait() {
    asm volatile("cp.async.wait_group %0;" :: "n"(N));
}
__device__ __forceinline__ void ldsm_x4(uint32_t& r0, uint32_t& r1, uint32_t& r2, uint32_t& r3,
                                        uint32_t addr) {
    asm volatile("ldmatrix.sync.aligned.m8n8.x4.shared.b16 {%0,%1,%2,%3}, [%4];"
                 : "=r"(r0), "=r"(r1), "=r"(r2), "=r"(r3) : "r"(addr));
}

// ---------------------------------------------------------------------------
// 1) fold: Wa (fp32), combined bias, qkv weights in B-frag order (proven R6)
// ---------------------------------------------------------------------------
__global__ void fold_k(const float* __restrict__ dwq, const float* __restrict__ pwq,
                       const float* __restrict__ bq,
                       const float* __restrict__ dwk, const float* __restrict__ pwk,
                       const float* __restrict__ bk,
                       const float* __restrict__ dwv, const float* __restrict__ pwv,
                       const float* __restrict__ bv,
                       const float* __restrict__ dwa, const float* __restrict__ pwa) {
    const int idx = blockIdx.x * 256 + threadIdx.x;   // 0..24575
    if (idx < 16384) {
        const int cr = idx >> 8;
        g_Wa[idx] = dwa[cr] * pwa[idx];
    }
    if (idx < 192)
        g_b192[idx] = (idx < 64) ? bq[idx] : (idx < 128 ? bk[idx - 64] : bv[idx - 128]);

    const int nn = idx >> 7;       // output unit 0..191
    const int p  = idx & 127;      // c-pair 0..127
    const int c0 = 2 * p, c1 = 2 * p + 1;
    float w0, w1;
    if (nn < 64)       { w0 = dwq[c0] * pwq[c0 * 64 + nn];        w1 = dwq[c1] * pwq[c1 * 64 + nn]; }
    else if (nn < 128) { const int m = nn - 64;  w0 = dwk[c0] * pwk[c0 * 64 + m]; w1 = dwk[c1] * pwk[c1 * 64 + m]; }
    else               { const int m = nn - 128; w0 = dwv[c0] * pwv[c0 * 64 + m]; w1 = dwv[c1] * pwv[c1 * 64 + m]; }
    const int h = nn / 96, nl = nn % 96, nt = nl >> 3, r = nl & 7;
    const int ks = p >> 3, rem = p & 7, q = rem & 3, slot = rem >> 2;
    g_Wfrag[(((h * 12 + nt) * 16 + ks) * 32 + r * 4 + q) * 2 + slot] = packbf2(w0, w1);
}

// ---------------------------------------------------------------------------
// 2) QKV projection via mma.sync (proven R6)
// ---------------------------------------------------------------------------
__global__ __launch_bounds__(256) void proj_k(const float* __restrict__ X) {
    __shared__ uint32_t sW[12288];   // 48 KB
    const int tid = threadIdx.x, lane = tid & 31, w = tid >> 5;
    const int r = lane >> 2, q = lane & 3;
    const int m0 = blockIdx.x * 128, h = blockIdx.y;

    const uint32_t swb = s2u(sW);
    const uint32_t* Wsrc = g_Wfrag + h * 12288;
    for (int t = tid; t < 3072; t += 256) cpasync16(swb + t * 16, Wsrc + t * 4);
    cpcommit(); cpwait<0>(); __syncthreads();

    float acc[12][4];
#pragma unroll
    for (int nt = 0; nt < 12; nt++) {
        const int n0 = h * 96 + nt * 8 + 2 * q;
        const float b0 = g_b192[n0], b1 = g_b192[n0 + 1];
        acc[nt][0] = b0; acc[nt][1] = b1; acc[nt][2] = b0; acc[nt][3] = b1;
    }

    const int mA = m0 + 16 * w + r;
    const float2* X2 = (const float2*)X;
    const uint2* sW2 = (const uint2*)sW;
#pragma unroll 4
    for (int ks = 0; ks < 16; ks++) {
        const float2 u0 = X2[(size_t)mA * 128 + ks * 8 + q];
        const float2 u1 = X2[(size_t)(mA + 8) * 128 + ks * 8 + q];
        const float2 u2 = X2[(size_t)mA * 128 + ks * 8 + q + 4];
        const float2 u3 = X2[(size_t)(mA + 8) * 128 + ks * 8 + q + 4];
        const uint32_t a0 = packbf2(u0.x, u0.y);
        const uint32_t a1 = packbf2(u1.x, u1.y);
        const uint32_t a2 = packbf2(u2.x, u2.y);
        const uint32_t a3 = packbf2(u3.x, u3.y);
#pragma unroll
        for (int nt = 0; nt < 12; nt++) {
            const uint2 b = sW2[(nt * 16 + ks) * 32 + lane];
            mma16816(acc[nt][0], acc[nt][1], acc[nt][2], acc[nt][3], a0, a1, a2, a3, b.x, b.y);
        }
    }

    uint32_t* Qw = (uint32_t*)g_Qb;
    uint32_t* Kw = (uint32_t*)g_Kb;
    const int nb = mA >> 12, ii = mA & 4095;
#pragma unroll
    for (int nt = 0; nt < 12; nt++) {
        const int n0 = h * 96 + nt * 8 + 2 * q;
        if (n0 < 64) {
            Qw[(size_t)mA * 32 + (n0 >> 1)]       = packbf2(acc[nt][0], acc[nt][1]);
            Qw[(size_t)(mA + 8) * 32 + (n0 >> 1)] = packbf2(acc[nt][2], acc[nt][3]);
        } else if (n0 < 128) {
            const int k0 = n0 - 64;
            Kw[(size_t)mA * 32 + (k0 >> 1)]       = packbf2(acc[nt][0], acc[nt][1]);
            Kw[(size_t)(mA + 8) * 32 + (k0 >> 1)] = packbf2(acc[nt][2], acc[nt][3]);
        } else {
            const int c = n0 - 128;
            g_Vtb[((size_t)nb * 64 + c) * HW + ii]          = __float2bfloat16(acc[nt][0]);
            g_Vtb[((size_t)nb * 64 + c + 1) * HW + ii]      = __float2bfloat16(acc[nt][1]);
            g_Vtb[((size_t)nb * 64 + c) * HW + ii + 8]      = __float2bfloat16(acc[nt][2]);
            g_Vtb[((size_t)nb * 64 + c + 1) * HW + ii + 8]  = __float2bfloat16(acc[nt][3]);
        }
    }
}

// ---------------------------------------------------------------------------
// 3) Pass A: rowsum partials over a j-quarter (proven R6)
// ---------------------------------------------------------------------------
__global__ __launch_bounds__(128) void rowsum_k() {
    __shared__ uint32_t sQ[2][128 * 36];
    const int tid = threadIdx.x, lane = tid & 31, w = tid >> 5;
    const int r = lane >> 2, q = lane & 3;
    const int i0 = blockIdx.x * 64, jq = blockIdx.y, n = blockIdx.z;

    uint32_t a[4][4];
    const uint32_t* Kg = (const uint32_t*)g_Kb + (size_t)n * HW * 32;
#pragma unroll
    for (int ks = 0; ks < 4; ks++) {
        const uint32_t* kr = Kg + (size_t)(i0 + 16 * w + r) * 32 + ks * 8 + q;
        a[ks][0] = kr[0]; a[ks][1] = kr[256]; a[ks][2] = kr[4]; a[ks][3] = kr[260];
    }
    const uint32_t* Qg = (const uint32_t*)g_Qb + ((size_t)n * HW + jq * 1024) * 32;
    const uint32_t sqb0 = s2u(sQ[0]), sqb1 = s2u(sQ[1]);
    const uint32_t loff = (lane & 7) * 144 + (lane >> 3) * 16;

    auto issue = [&](int ch, uint32_t base) {
#pragma unroll
        for (int t = tid; t < 1024; t += 128) {
            const int row = t >> 3, c4 = (t & 7) * 4;
            cpasync16(base + row * 144 + c4 * 4, Qg + (size_t)(ch * 128 + row) * 32 + c4);
        }
    };
    issue(0, sqb0); cpcommit();

    float sA = 0.f, sB = 0.f;
    for (int ch = 0; ch < 8; ch++) {
        if (ch < 7) { issue(ch + 1, (ch & 1) ? sqb0 : sqb1); cpcommit(); cpwait<1>(); }
        else cpwait<0>();
        __syncthreads();
        const uint32_t base = (ch & 1) ? sqb1 : sqb0;
#pragma unroll 4
        for (int nt = 0; nt < 16; nt++) {
            uint32_t b00, b10, b01, b11, b02, b12, b03, b13;
            ldsm_x4(b00, b10, b01, b11, base + nt * 1152 + loff);
            ldsm_x4(b02, b12, b03, b13, base + nt * 1152 + 64 + loff);
            float c0 = 0.f, c1 = 0.f, c2 = 0.f, c3 = 0.f;
            mma16816(c0, c1, c2, c3, a[0][0], a[0][1], a[0][2], a[0][3], b00, b10);
            mma16816(c0, c1, c2, c3, a[1][0], a[1][1], a[1][2], a[1][3], b01, b11);
            mma16816(c0, c1, c2, c3, a[2][0], a[2][1], a[2][2], a[2][3], b02, b12);
            mma16816(c0, c1, c2, c3, a[3][0], a[3][1], a[3][2], a[3][3], b03, b13);
            sA += __expf(c0) + __expf(c1);
            sB += __expf(c2) + __expf(c3);
        }
        __syncthreads();
    }
    sA += __shfl_xor_sync(0xffffffffu, sA, 1);
    sA += __shfl_xor_sync(0xffffffffu, sA, 2);
    sB += __shfl_xor_sync(0xffffffffu, sB, 1);
    sB += __shfl_xor_sync(0xffffffffu, sB, 2);
    if (q == 0) {
        g_part[jq][n * HW + i0 + 16 * w + r]     = sA;
        g_part[jq][n * HW + i0 + 16 * w + r + 8] = sB;
    }
}

// ---------------------------------------------------------------------------
// 4) Pass B over an i-quarter (1024 i). Block = (64-j, ih:0..3, n), 128 thr.
//    inv computed from 4 rowsum partials into smem at block start (no inv_k).
// ---------------------------------------------------------------------------
__global__ __launch_bounds__(128) void attn_k() {
    __shared__ uint32_t sK[2][64 * 36];
    __shared__ uint32_t sVt[2][64 * 36];
    __shared__ float sInvAll[1024];
    const int tid = threadIdx.x, lane = tid & 31, w = tid >> 5;
    const int r = lane >> 2, q = lane & 3;
    const int j0 = blockIdx.x * 64, ih = blockIdx.y, n = blockIdx.z;

    // inv table for this block's whole i-range
    for (int t = tid; t < 1024; t += 128) {
        const int gi = n * HW + ih * 1024 + t;
        sInvAll[t] = __frcp_rn(g_part[0][gi] + g_part[1][gi] + g_part[2][gi] + g_part[3][gi]);
    }

    uint32_t aq[4][4];
    const uint32_t* Qg = (const uint32_t*)g_Qb + (size_t)n * HW * 32;
#pragma unroll
    for (int ks = 0; ks < 4; ks++) {
        const uint32_t* qr = Qg + (size_t)(j0 + 16 * w + r) * 32 + ks * 8 + q;
        aq[ks][0] = qr[0]; aq[ks][1] = qr[256]; aq[ks][2] = qr[4]; aq[ks][3] = qr[260];
    }
    const uint32_t* Kg = (const uint32_t*)g_Kb + (size_t)n * HW * 32;
    const uint32_t* Vg = (const uint32_t*)g_Vtb + (size_t)n * CR * (HW / 2);

    const uint32_t skb[2] = {s2u(sK[0]),  s2u(sK[1])};
    const uint32_t svb[2] = {s2u(sVt[0]), s2u(sVt[1])};
    const uint32_t loff1 = (lane & 7) * 144 + (lane >> 3) * 16;
    const uint32_t loff2 = (lane & 7) * 144 + ((lane >> 3) & 1) * 16 + (lane >> 4) * 1152;

    auto issue = [&](int ch, int buf) {
        const int i0 = ih * 1024 + ch * 64;
#pragma unroll
        for (int t = tid; t < 512; t += 128) {
            const int row = t >> 3, c4 = (t & 7) * 4;
            cpasync16(skb[buf] + row * 144 + c4 * 4, Kg + (size_t)(i0 + row) * 32 + c4);
            cpasync16(svb[buf] + row * 144 + c4 * 4, Vg + (size_t)row * 2048 + (i0 >> 1) + c4);
        }
    };

    float acc[8][4];
#pragma unroll
    for (int ct = 0; ct < 8; ct++)
        acc[ct][0] = acc[ct][1] = acc[ct][2] = acc[ct][3] = 0.f;

    issue(0, 0); cpcommit();
    for (int ch = 0; ch < 16; ch++) {
        if (ch < 15) { issue(ch + 1, (ch + 1) & 1); cpcommit(); cpwait<1>(); }
        else cpwait<0>();
        __syncthreads();
        const int buf = ch & 1;
        const uint32_t kb = skb[buf], vb = svb[buf];
        const float* iv = sInvAll + ch * 64;

#pragma unroll
        for (int ks2 = 0; ks2 < 4; ks2++) {
            uint32_t ap[4];
#pragma unroll
            for (int half = 0; half < 2; half++) {
                const int nt = 2 * ks2 + half;
                uint32_t b00, b10, b01, b11, b02, b12, b03, b13;
                ldsm_x4(b00, b10, b01, b11, kb + nt * 1152 + loff1);
                ldsm_x4(b02, b12, b03, b13, kb + nt * 1152 + 64 + loff1);
                float c0 = 0.f, c1 = 0.f, c2 = 0.f, c3 = 0.f;
                mma16816(c0, c1, c2, c3, aq[0][0], aq[0][1], aq[0][2], aq[0][3], b00, b10);
                mma16816(c0, c1, c2, c3, aq[1][0], aq[1][1], aq[1][2], aq[1][3], b01, b11);
                mma16816(c0, c1, c2, c3, aq[2][0], aq[2][1], aq[2][2], aq[2][3], b02, b12);
                mma16816(c0, c1, c2, c3, aq[3][0], aq[3][1], aq[3][2], aq[3][3], b03, b13);
                const float i0v = iv[nt * 8 + 2 * q];
                const float i1v = iv[nt * 8 + 2 * q + 1];
                ap[half]     = packbf2(__expf(c0) * i0v, __expf(c1) * i1v);
                ap[2 + half] = packbf2(__expf(c2) * i0v, __expf(c3) * i1v);
            }
#pragma unroll
            for (int ctp = 0; ctp < 4; ctp++) {
                uint32_t v0, v1, v2, v3;
                ldsm_x4(v0, v1, v2, v3, vb + ctp * 2304 + ks2 * 32 + loff2);
                mma16816(acc[2 * ctp][0], acc[2 * ctp][1], acc[2 * ctp][2], acc[2 * ctp][3],
                         ap[0], ap[2], ap[1], ap[3], v0, v1);
                mma16816(acc[2 * ctp + 1][0], acc[2 * ctp + 1][1], acc[2 * ctp + 1][2], acc[2 * ctp + 1][3],
                         ap[0], ap[2], ap[1], ap[3], v2, v3);
            }
        }
        __syncthreads();
    }

    float* A = g_attp[ih] + (size_t)n * CR * HW;
    const int jrow = j0 + 16 * w + r;
#pragma unroll
    for (int ct = 0; ct < 8; ct++) {
        const int c = ct * 8 + 2 * q;
        A[(size_t)c * HW + jrow]           = acc[ct][0];
        A[(size_t)(c + 1) * HW + jrow]     = acc[ct][1];
        A[(size_t)c * HW + jrow + 8]       = acc[ct][2];
        A[(size_t)(c + 1) * HW + jrow + 8] = acc[ct][3];
    }
}

// ---------------------------------------------------------------------------
// 5) Final: block per (n,w); att 64x64 tile in smem; Wa column in registers.
//    att4[n,h,w,cr] = att[c=h][j=w*64+cr]; y = att4.Wa + ba; out = g*y + g
// ---------------------------------------------------------------------------
__global__ __launch_bounds__(256) void final_k(const float* __restrict__ G,
                                               const float* __restrict__ ba,
                                               float* __restrict__ out) {
    __shared__ float sa[64][68];
    const int b = blockIdx.x;
    const int n = b >> 6, w = b & 63;
    const int tid = threadIdx.x;

    for (int idx = tid; idx < 4096; idx += 256) {
        const int c = idx >> 6, cr = idx & 63;
        const size_t base = ((size_t)n * CR + c) * HW + w * 64 + cr;
        sa[c][cr] = g_attp[0][base] + g_attp[1][base] + g_attp[2][base] + g_attp[3][base];
    }
    __syncthreads();

    float wa[64];
#pragma unroll
    for (int cr = 0; cr < 64; cr++) wa[cr] = g_Wa[cr * CIN + tid];
    const float vba = ba[tid];

    size_t gidx = ((size_t)n * HW + w) * CIN + tid;
    for (int h = 0; h < 64; h++) {
        float acc = vba;
        const float4* row = (const float4*)sa[h];
#pragma unroll
        for (int k = 0; k < 16; k++) {
            const float4 v = row[k];
            acc = fmaf(v.x, wa[4 * k],     acc);
            acc = fmaf(v.y, wa[4 * k + 1], acc);
            acc = fmaf(v.z, wa[4 * k + 2], acc);
            acc = fmaf(v.w, wa[4 * k + 3], acc);
        }
        const float g = G[gidx];
        out[gidx] = fmaf(g, acc, g);
        gidx += (size_t)64 * CIN;
    }
}

// ---------------------------------------------------------------------------
extern "C" void kernel_launch(void* const* d_in, const int* in_sizes, int n_in,
                              void* d_out, int out_size) {
    const float* X   = (const float*)d_in[0];
    const float* G   = (const float*)d_in[1];
    const float* dwq = (const float*)d_in[2];
    const float* pwq = (const float*)d_in[3];
    const float* bq  = (const float*)d_in[4];
    const float* dwk = (const float*)d_in[5];
    const float* pwk = (const float*)d_in[6];
    const float* bk  = (const float*)d_in[7];
    const float* dwv = (const float*)d_in[8];
    const float* pwv = (const float*)d_in[9];
    const float* bv  = (const float*)d_in[10];
    const float* dwa = (const float*)d_in[11];
    const float* pwa = (const float*)d_in[12];
    const float* ba  = (const float*)d_in[13];
    float* out = (float*)d_out;

    const int N = in_sizes[0] / (HW * CIN);   // 4

    fold_k<<<96, 256>>>(dwq, pwq, bq, dwk, pwk, bk, dwv, pwv, bv, dwa, pwa);
    proj_k<<<dim3((N * HW) / 128, 2), 256>>>(X);
    rowsum_k<<<dim3(HW / 64, 4, N), 128>>>();
    attn_k<<<dim3(HW / 64, 4, N), 128>>>();
    final_k<<<N * 64, 256>>>(G, ba, out);
}

// round 8
// speedup vs baseline: 6.7486x; 1.0309x over previous
#include <cuda_runtime.h>
#include <cuda_bf16.h>
#include <stdint.h>

// Shapes fixed by the problem: N=4, H=W=64, C_in=256, C_red=64
constexpr int HW   = 4096;
constexpr int CIN  = 256;
constexpr int CR   = 64;
constexpr int MAXN = 4;

// ---------------- device scratch (allocation-free) ----------------
__device__ float g_Wa[CR * CIN];                          // fp32 [cr][cout]
__device__ uint32_t g_Wfrag[2 * 12288];                   // qkv weights in B-fragment order
__device__ float g_b192[192];
__device__ __nv_bfloat16 g_Qb[(size_t)MAXN * HW * CR];    // [n*HW + j][c]
__device__ __nv_bfloat16 g_Kb[(size_t)MAXN * HW * CR];    // [n*HW + i][c]
__device__ __nv_bfloat16 g_Vtb[(size_t)MAXN * CR * HW];   // [n][c][i]
__device__ float g_part[4][MAXN * HW];                    // rowsum partials (j-quarters)
__device__ float g_attp[4][(size_t)MAXN * CR * HW];       // att partials [ih][n][c][j]

// ---------------- helpers ----------------
__device__ __forceinline__ uint32_t s2u(const void* p) {
    return (uint32_t)__cvta_generic_to_shared(p);
}
__device__ __forceinline__ void mma16816(float& c0, float& c1, float& c2, float& c3,
                                         uint32_t a0, uint32_t a1, uint32_t a2, uint32_t a3,
                                         uint32_t b0, uint32_t b1) {
    asm volatile("mma.sync.aligned.m16n8k16.row.col.f32.bf16.bf16.f32 "
                 "{%0,%1,%2,%3}, {%4,%5,%6,%7}, {%8,%9}, {%0,%1,%2,%3};"
                 : "+f"(c0), "+f"(c1), "+f"(c2), "+f"(c3)
                 : "r"(a0), "r"(a1), "r"(a2), "r"(a3), "r"(b0), "r"(b1));
}
__device__ __forceinline__ uint32_t packbf2(float lo, float hi) {
    uint32_t d;
    asm("cvt.rn.bf16x2.f32 %0, %1, %2;" : "=r"(d) : "f"(hi), "f"(lo));
    return d;
}
__device__ __forceinline__ void cpasync16(uint32_t saddr, const void* g) {
    asm volatile("cp.async.ca.shared.global [%0], [%1], 16;" :: "r"(saddr), "l"(g));
}
__device__ __forceinline__ void cpcommit() { asm volatile("cp.async.commit_group;"); }
template<int N> __device__ __forceinline__ void cpwait() {
    asm volatile("cp.async.wait_group %0;" :: "n"(N));
}
__device__ __forceinline__ void ldsm_x4(uint32_t& r0, uint32_t& r1, uint32_t& r2, uint32_t& r3,
                                        uint32_t addr) {
    asm volatile("ldmatrix.sync.aligned.m8n8.x4.shared.b16 {%0,%1,%2,%3}, [%4];"
                 : "=r"(r0), "=r"(r1), "=r"(r2), "=r"(r3) : "r"(addr));
}

// ---------------------------------------------------------------------------
// 1) fold: Wa (fp32), combined bias, qkv weights in B-frag order (proven R6)
// ---------------------------------------------------------------------------
__global__ void fold_k(const float* __restrict__ dwq, const float* __restrict__ pwq,
                       const float* __restrict__ bq,
                       const float* __restrict__ dwk, const float* __restrict__ pwk,
                       const float* __restrict__ bk,
                       const float* __restrict__ dwv, const float* __restrict__ pwv,
                       const float* __restrict__ bv,
                       const float* __restrict__ dwa, const float* __restrict__ pwa) {
    const int idx = blockIdx.x * 256 + threadIdx.x;   // 0..24575
    if (idx < 16384) {
        const int cr = idx >> 8;
        g_Wa[idx] = dwa[cr] * pwa[idx];
    }
    if (idx < 192)
        g_b192[idx] = (idx < 64) ? bq[idx] : (idx < 128 ? bk[idx - 64] : bv[idx - 128]);

    const int nn = idx >> 7;       // output unit 0..191
    const int p  = idx & 127;      // c-pair 0..127
    const int c0 = 2 * p, c1 = 2 * p + 1;
    float w0, w1;
    if (nn < 64)       { w0 = dwq[c0] * pwq[c0 * 64 + nn];        w1 = dwq[c1] * pwq[c1 * 64 + nn]; }
    else if (nn < 128) { const int m = nn - 64;  w0 = dwk[c0] * pwk[c0 * 64 + m]; w1 = dwk[c1] * pwk[c1 * 64 + m]; }
    else               { const int m = nn - 128; w0 = dwv[c0] * pwv[c0 * 64 + m]; w1 = dwv[c1] * pwv[c1 * 64 + m]; }
    const int h = nn / 96, nl = nn % 96, nt = nl >> 3, r = nl & 7;
    const int ks = p >> 3, rem = p & 7, q = rem & 3, slot = rem >> 2;
    g_Wfrag[(((h * 12 + nt) * 16 + ks) * 32 + r * 4 + q) * 2 + slot] = packbf2(w0, w1);
}

// ---------------------------------------------------------------------------
// 2) QKV projection via mma.sync (proven R6)
// ---------------------------------------------------------------------------
__global__ __launch_bounds__(256) void proj_k(const float* __restrict__ X) {
    __shared__ uint32_t sW[12288];   // 48 KB
    const int tid = threadIdx.x, lane = tid & 31, w = tid >> 5;
    const int r = lane >> 2, q = lane & 3;
    const int m0 = blockIdx.x * 128, h = blockIdx.y;

    const uint32_t swb = s2u(sW);
    const uint32_t* Wsrc = g_Wfrag + h * 12288;
    for (int t = tid; t < 3072; t += 256) cpasync16(swb + t * 16, Wsrc + t * 4);
    cpcommit(); cpwait<0>(); __syncthreads();

    float acc[12][4];
#pragma unroll
    for (int nt = 0; nt < 12; nt++) {
        const int n0 = h * 96 + nt * 8 + 2 * q;
        const float b0 = g_b192[n0], b1 = g_b192[n0 + 1];
        acc[nt][0] = b0; acc[nt][1] = b1; acc[nt][2] = b0; acc[nt][3] = b1;
    }

    const int mA = m0 + 16 * w + r;
    const float2* X2 = (const float2*)X;
    const uint2* sW2 = (const uint2*)sW;
#pragma unroll 4
    for (int ks = 0; ks < 16; ks++) {
        const float2 u0 = X2[(size_t)mA * 128 + ks * 8 + q];
        const float2 u1 = X2[(size_t)(mA + 8) * 128 + ks * 8 + q];
        const float2 u2 = X2[(size_t)mA * 128 + ks * 8 + q + 4];
        const float2 u3 = X2[(size_t)(mA + 8) * 128 + ks * 8 + q + 4];
        const uint32_t a0 = packbf2(u0.x, u0.y);
        const uint32_t a1 = packbf2(u1.x, u1.y);
        const uint32_t a2 = packbf2(u2.x, u2.y);
        const uint32_t a3 = packbf2(u3.x, u3.y);
#pragma unroll
        for (int nt = 0; nt < 12; nt++) {
            const uint2 b = sW2[(nt * 16 + ks) * 32 + lane];
            mma16816(acc[nt][0], acc[nt][1], acc[nt][2], acc[nt][3], a0, a1, a2, a3, b.x, b.y);
        }
    }

    uint32_t* Qw = (uint32_t*)g_Qb;
    uint32_t* Kw = (uint32_t*)g_Kb;
    const int nb = mA >> 12, ii = mA & 4095;
#pragma unroll
    for (int nt = 0; nt < 12; nt++) {
        const int n0 = h * 96 + nt * 8 + 2 * q;
        if (n0 < 64) {
            Qw[(size_t)mA * 32 + (n0 >> 1)]       = packbf2(acc[nt][0], acc[nt][1]);
            Qw[(size_t)(mA + 8) * 32 + (n0 >> 1)] = packbf2(acc[nt][2], acc[nt][3]);
        } else if (n0 < 128) {
            const int k0 = n0 - 64;
            Kw[(size_t)mA * 32 + (k0 >> 1)]       = packbf2(acc[nt][0], acc[nt][1]);
            Kw[(size_t)(mA + 8) * 32 + (k0 >> 1)] = packbf2(acc[nt][2], acc[nt][3]);
        } else {
            const int c = n0 - 128;
            g_Vtb[((size_t)nb * 64 + c) * HW + ii]          = __float2bfloat16(acc[nt][0]);
            g_Vtb[((size_t)nb * 64 + c + 1) * HW + ii]      = __float2bfloat16(acc[nt][1]);
            g_Vtb[((size_t)nb * 64 + c) * HW + ii + 8]      = __float2bfloat16(acc[nt][2]);
            g_Vtb[((size_t)nb * 64 + c + 1) * HW + ii + 8]  = __float2bfloat16(acc[nt][3]);
        }
    }
}

// ---------------------------------------------------------------------------
// 3) Pass A: rowsum partials over a j-quarter. 32 i-rows per warp (2 A-sets),
//    128-i tile per block. B-fragment LDSM amortized over both sets.
// ---------------------------------------------------------------------------
__global__ __launch_bounds__(128) void rowsum_k() {
    __shared__ uint32_t sQ[2][128 * 36];
    const int tid = threadIdx.x, lane = tid & 31, w = tid >> 5;
    const int r = lane >> 2, q = lane & 3;
    const int i0 = blockIdx.x * 128, jq = blockIdx.y, n = blockIdx.z;

    uint32_t a[2][4][4];
    const uint32_t* Kg = (const uint32_t*)g_Kb + (size_t)n * HW * 32;
#pragma unroll
    for (int s = 0; s < 2; s++)
#pragma unroll
        for (int ks = 0; ks < 4; ks++) {
            const uint32_t* kr = Kg + (size_t)(i0 + 32 * w + 16 * s + r) * 32 + ks * 8 + q;
            a[s][ks][0] = kr[0]; a[s][ks][1] = kr[256]; a[s][ks][2] = kr[4]; a[s][ks][3] = kr[260];
        }
    const uint32_t* Qg = (const uint32_t*)g_Qb + ((size_t)n * HW + jq * 1024) * 32;
    const uint32_t sqb0 = s2u(sQ[0]), sqb1 = s2u(sQ[1]);
    const uint32_t loff = (lane & 7) * 144 + (lane >> 3) * 16;

    auto issue = [&](int ch, uint32_t base) {
#pragma unroll
        for (int t = tid; t < 1024; t += 128) {
            const int row = t >> 3, c4 = (t & 7) * 4;
            cpasync16(base + row * 144 + c4 * 4, Qg + (size_t)(ch * 128 + row) * 32 + c4);
        }
    };
    issue(0, sqb0); cpcommit();

    float sA[2] = {0.f, 0.f}, sB[2] = {0.f, 0.f};
    for (int ch = 0; ch < 8; ch++) {
        if (ch < 7) { issue(ch + 1, (ch & 1) ? sqb0 : sqb1); cpcommit(); cpwait<1>(); }
        else cpwait<0>();
        __syncthreads();
        const uint32_t base = (ch & 1) ? sqb1 : sqb0;
#pragma unroll 4
        for (int nt = 0; nt < 16; nt++) {
            uint32_t b00, b10, b01, b11, b02, b12, b03, b13;
            ldsm_x4(b00, b10, b01, b11, base + nt * 1152 + loff);
            ldsm_x4(b02, b12, b03, b13, base + nt * 1152 + 64 + loff);
#pragma unroll
            for (int s = 0; s < 2; s++) {
                float c0 = 0.f, c1 = 0.f, c2 = 0.f, c3 = 0.f;
                mma16816(c0, c1, c2, c3, a[s][0][0], a[s][0][1], a[s][0][2], a[s][0][3], b00, b10);
                mma16816(c0, c1, c2, c3, a[s][1][0], a[s][1][1], a[s][1][2], a[s][1][3], b01, b11);
                mma16816(c0, c1, c2, c3, a[s][2][0], a[s][2][1], a[s][2][2], a[s][2][3], b02, b12);
                mma16816(c0, c1, c2, c3, a[s][3][0], a[s][3][1], a[s][3][2], a[s][3][3], b03, b13);
                sA[s] += __expf(c0) + __expf(c1);
                sB[s] += __expf(c2) + __expf(c3);
            }
        }
        __syncthreads();
    }
#pragma unroll
    for (int s = 0; s < 2; s++) {
        float va = sA[s], vb = sB[s];
        va += __shfl_xor_sync(0xffffffffu, va, 1);
        va += __shfl_xor_sync(0xffffffffu, va, 2);
        vb += __shfl_xor_sync(0xffffffffu, vb, 1);
        vb += __shfl_xor_sync(0xffffffffu, vb, 2);
        if (q == 0) {
            g_part[jq][n * HW + i0 + 32 * w + 16 * s + r]     = va;
            g_part[jq][n * HW + i0 + 32 * w + 16 * s + r + 8] = vb;
        }
    }
}

// ---------------------------------------------------------------------------
// 4) Pass B over an i-quarter. 32 j-rows per warp (2 A-sets), 128-j tile per
//    block. K/V B-fragment LDSM + cp.async amortized over both sets.
// ---------------------------------------------------------------------------
__global__ __launch_bounds__(128) void attn_k() {
    __shared__ uint32_t sK[2][64 * 36];
    __shared__ uint32_t sVt[2][64 * 36];
    __shared__ float sInvAll[1024];
    const int tid = threadIdx.x, lane = tid & 31, w = tid >> 5;
    const int r = lane >> 2, q = lane & 3;
    const int j0 = blockIdx.x * 128, ih = blockIdx.y, n = blockIdx.z;

    for (int t = tid; t < 1024; t += 128) {
        const int gi = n * HW + ih * 1024 + t;
        sInvAll[t] = __frcp_rn(g_part[0][gi] + g_part[1][gi] + g_part[2][gi] + g_part[3][gi]);
    }

    uint32_t aq[2][4][4];
    const uint32_t* Qg = (const uint32_t*)g_Qb + (size_t)n * HW * 32;
#pragma unroll
    for (int s = 0; s < 2; s++)
#pragma unroll
        for (int ks = 0; ks < 4; ks++) {
            const uint32_t* qr = Qg + (size_t)(j0 + 32 * w + 16 * s + r) * 32 + ks * 8 + q;
            aq[s][ks][0] = qr[0]; aq[s][ks][1] = qr[256]; aq[s][ks][2] = qr[4]; aq[s][ks][3] = qr[260];
        }
    const uint32_t* Kg = (const uint32_t*)g_Kb + (size_t)n * HW * 32;
    const uint32_t* Vg = (const uint32_t*)g_Vtb + (size_t)n * CR * (HW / 2);

    const uint32_t skb[2] = {s2u(sK[0]),  s2u(sK[1])};
    const uint32_t svb[2] = {s2u(sVt[0]), s2u(sVt[1])};
    const uint32_t loff1 = (lane & 7) * 144 + (lane >> 3) * 16;
    const uint32_t loff2 = (lane & 7) * 144 + ((lane >> 3) & 1) * 16 + (lane >> 4) * 1152;

    auto issue = [&](int ch, int buf) {
        const int i0 = ih * 1024 + ch * 64;
#pragma unroll
        for (int t = tid; t < 512; t += 128) {
            const int row = t >> 3, c4 = (t & 7) * 4;
            cpasync16(skb[buf] + row * 144 + c4 * 4, Kg + (size_t)(i0 + row) * 32 + c4);
            cpasync16(svb[buf] + row * 144 + c4 * 4, Vg + (size_t)row * 2048 + (i0 >> 1) + c4);
        }
    };

    float acc[2][8][4];
#pragma unroll
    for (int s = 0; s < 2; s++)
#pragma unroll
        for (int ct = 0; ct < 8; ct++)
            acc[s][ct][0] = acc[s][ct][1] = acc[s][ct][2] = acc[s][ct][3] = 0.f;

    issue(0, 0); cpcommit();
    for (int ch = 0; ch < 16; ch++) {
        if (ch < 15) { issue(ch + 1, (ch + 1) & 1); cpcommit(); cpwait<1>(); }
        else cpwait<0>();
        __syncthreads();
        const int buf = ch & 1;
        const uint32_t kb = skb[buf], vb = svb[buf];
        const float* iv = sInvAll + ch * 64;

#pragma unroll
        for (int ks2 = 0; ks2 < 4; ks2++) {
            uint32_t ap[2][4];
#pragma unroll
            for (int half = 0; half < 2; half++) {
                const int nt = 2 * ks2 + half;
                uint32_t b00, b10, b01, b11, b02, b12, b03, b13;
                ldsm_x4(b00, b10, b01, b11, kb + nt * 1152 + loff1);
                ldsm_x4(b02, b12, b03, b13, kb + nt * 1152 + 64 + loff1);
                const float i0v = iv[nt * 8 + 2 * q];
                const float i1v = iv[nt * 8 + 2 * q + 1];
#pragma unroll
                for (int s = 0; s < 2; s++) {
                    float c0 = 0.f, c1 = 0.f, c2 = 0.f, c3 = 0.f;
                    mma16816(c0, c1, c2, c3, aq[s][0][0], aq[s][0][1], aq[s][0][2], aq[s][0][3], b00, b10);
                    mma16816(c0, c1, c2, c3, aq[s][1][0], aq[s][1][1], aq[s][1][2], aq[s][1][3], b01, b11);
                    mma16816(c0, c1, c2, c3, aq[s][2][0], aq[s][2][1], aq[s][2][2], aq[s][2][3], b02, b12);
                    mma16816(c0, c1, c2, c3, aq[s][3][0], aq[s][3][1], aq[s][3][2], aq[s][3][3], b03, b13);
                    ap[s][half]     = packbf2(__expf(c0) * i0v, __expf(c1) * i1v);
                    ap[s][2 + half] = packbf2(__expf(c2) * i0v, __expf(c3) * i1v);
                }
            }
#pragma unroll
            for (int ctp = 0; ctp < 4; ctp++) {
                uint32_t v0, v1, v2, v3;
                ldsm_x4(v0, v1, v2, v3, vb + ctp * 2304 + ks2 * 32 + loff2);
#pragma unroll
                for (int s = 0; s < 2; s++) {
                    mma16816(acc[s][2 * ctp][0], acc[s][2 * ctp][1], acc[s][2 * ctp][2], acc[s][2 * ctp][3],
                             ap[s][0], ap[s][2], ap[s][1], ap[s][3], v0, v1);
                    mma16816(acc[s][2 * ctp + 1][0], acc[s][2 * ctp + 1][1], acc[s][2 * ctp + 1][2], acc[s][2 * ctp + 1][3],
                             ap[s][0], ap[s][2], ap[s][1], ap[s][3], v2, v3);
                }
            }
        }
        __syncthreads();
    }

    float* A = g_attp[ih] + (size_t)n * CR * HW;
#pragma unroll
    for (int s = 0; s < 2; s++) {
        const int jrow = j0 + 32 * w + 16 * s + r;
#pragma unroll
        for (int ct = 0; ct < 8; ct++) {
            const int c = ct * 8 + 2 * q;
            A[(size_t)c * HW + jrow]           = acc[s][ct][0];
            A[(size_t)(c + 1) * HW + jrow]     = acc[s][ct][1];
            A[(size_t)c * HW + jrow + 8]       = acc[s][ct][2];
            A[(size_t)(c + 1) * HW + jrow + 8] = acc[s][ct][3];
        }
    }
}

// ---------------------------------------------------------------------------
// 5) Final (proven R7): block per (n,w); Wa column in registers.
// ---------------------------------------------------------------------------
__global__ __launch_bounds__(256) void final_k(const float* __restrict__ G,
                                               const float* __restrict__ ba,
                                               float* __restrict__ out) {
    __shared__ float sa[64][68];
    const int b = blockIdx.x;
    const int n = b >> 6, w = b & 63;
    const int tid = threadIdx.x;

    for (int idx = tid; idx < 4096; idx += 256) {
        const int c = idx >> 6, cr = idx & 63;
        const size_t base = ((size_t)n * CR + c) * HW + w * 64 + cr;
        sa[c][cr] = g_attp[0][base] + g_attp[1][base] + g_attp[2][base] + g_attp[3][base];
    }
    __syncthreads();

    float wa[64];
#pragma unroll
    for (int cr = 0; cr < 64; cr++) wa[cr] = g_Wa[cr * CIN + tid];
    const float vba = ba[tid];

    size_t gidx = ((size_t)n * HW + w) * CIN + tid;
    for (int h = 0; h < 64; h++) {
        float acc = vba;
        const float4* row = (const float4*)sa[h];
#pragma unroll
        for (int k = 0; k < 16; k++) {
            const float4 v = row[k];
            acc = fmaf(v.x, wa[4 * k],     acc);
            acc = fmaf(v.y, wa[4 * k + 1], acc);
            acc = fmaf(v.z, wa[4 * k + 2], acc);
            acc = fmaf(v.w, wa[4 * k + 3], acc);
        }
        const float g = G[gidx];
        out[gidx] = fmaf(g, acc, g);
        gidx += (size_t)64 * CIN;
    }
}

// ---------------------------------------------------------------------------
extern "C" void kernel_launch(void* const* d_in, const int* in_sizes, int n_in,
                              void* d_out, int out_size) {
    const float* X   = (const float*)d_in[0];
    const float* G   = (const float*)d_in[1];
    const float* dwq = (const float*)d_in[2];
    const float* pwq = (const float*)d_in[3];
    const float* bq  = (const float*)d_in[4];
    const float* dwk = (const float*)d_in[5];
    const float* pwk = (const float*)d_in[6];
    const float* bk  = (const float*)d_in[7];
    const float* dwv = (const float*)d_in[8];
    const float* pwv = (const float*)d_in[9];
    const float* bv  = (const float*)d_in[10];
    const float* dwa = (const float*)d_in[11];
    const float* pwa = (const float*)d_in[12];
    const float* ba  = (const float*)d_in[13];
    float* out = (float*)d_out;

    const int N = in_sizes[0] / (HW * CIN);   // 4

    fold_k<<<96, 256>>>(dwq, pwq, bq, dwk, pwk, bk, dwv, pwv, bv, dwa, pwa);
    proj_k<<<dim3((N * HW) / 128, 2), 256>>>(X);
    rowsum_k<<<dim3(HW / 128, 4, N), 128>>>();
    attn_k<<<dim3(HW / 128, 4, N), 128>>>();
    final_k<<<N * 64, 256>>>(G, ba, out);
}

// round 9
// speedup vs baseline: 6.7807x; 1.0048x over previous
#include <cuda_runtime.h>
#include <cuda_fp16.h>
#include <stdint.h>

// Shapes fixed by the problem: N=4, H=W=64, C_in=256, C_red=64
constexpr int HW   = 4096;
constexpr int CIN  = 256;
constexpr int CR   = 64;
constexpr int MAXN = 4;

// ---------------- device scratch (allocation-free) ----------------
__device__ float g_Wa[CR * CIN];                          // fp32 [cr][cout]
__device__ uint32_t g_Wfrag[2 * 12288];                   // qkv weights in B-fragment order (f16x2)
__device__ float g_b192[192];
__device__ __half g_Qh[(size_t)MAXN * HW * CR];           // [n*HW + j][c]
__device__ __half g_Kh[(size_t)MAXN * HW * CR];           // [n*HW + i][c]
__device__ __half g_Vth[(size_t)MAXN * CR * HW];          // [n][c][i]
__device__ float g_part[4][MAXN * HW];                    // rowsum partials (j-quarters)
__device__ float g_attp[4][(size_t)MAXN * CR * HW];       // att partials [ih][n][c][j]

// ---------------- helpers ----------------
__device__ __forceinline__ uint32_t s2u(const void* p) {
    return (uint32_t)__cvta_generic_to_shared(p);
}
// f32-accumulate f16-input mma (for proj)
__device__ __forceinline__ void mma16816(float& c0, float& c1, float& c2, float& c3,
                                         uint32_t a0, uint32_t a1, uint32_t a2, uint32_t a3,
                                         uint32_t b0, uint32_t b1) {
    asm volatile("mma.sync.aligned.m16n8k16.row.col.f32.f16.f16.f32 "
                 "{%0,%1,%2,%3}, {%4,%5,%6,%7}, {%8,%9}, {%0,%1,%2,%3};"
                 : "+f"(c0), "+f"(c1), "+f"(c2), "+f"(c3)
                 : "r"(a0), "r"(a1), "r"(a2), "r"(a3), "r"(b0), "r"(b1));
}
// f16-accumulate f16 mma (2x rate) — D/C are two f16x2 regs
__device__ __forceinline__ void mma16816h(uint32_t& d0, uint32_t& d1,
                                          uint32_t a0, uint32_t a1, uint32_t a2, uint32_t a3,
                                          uint32_t b0, uint32_t b1) {
    asm volatile("mma.sync.aligned.m16n8k16.row.col.f16.f16.f16.f16 "
                 "{%0,%1}, {%2,%3,%4,%5}, {%6,%7}, {%0,%1};"
                 : "+r"(d0), "+r"(d1)
                 : "r"(a0), "r"(a1), "r"(a2), "r"(a3), "r"(b0), "r"(b1));
}
__device__ __forceinline__ uint32_t packf16(float lo, float hi) {
    uint32_t d;
    asm("cvt.rn.f16x2.f32 %0, %1, %2;" : "=r"(d) : "f"(hi), "f"(lo));
    return d;
}
__device__ __forceinline__ float2 unpackh2(uint32_t u) {
    __half2 h = *reinterpret_cast<__half2*>(&u);
    return __half22float2(h);
}
__device__ __forceinline__ void cpasync16(uint32_t saddr, const void* g) {
    asm volatile("cp.async.ca.shared.global [%0], [%1], 16;" :: "r"(saddr), "l"(g));
}
__device__ __forceinline__ void cpcommit() { asm volatile("cp.async.commit_group;"); }
template<int N> __device__ __forceinline__ void cpwait() {
    asm volatile("cp.async.wait_group %0;" :: "n"(N));
}
__device__ __forceinline__ void ldsm_x4(uint32_t& r0, uint32_t& r1, uint32_t& r2, uint32_t& r3,
                                        uint32_t addr) {
    asm volatile("ldmatrix.sync.aligned.m8n8.x4.shared.b16 {%0,%1,%2,%3}, [%4];"
                 : "=r"(r0), "=r"(r1), "=r"(r2), "=r"(r3) : "r"(addr));
}

// ---------------------------------------------------------------------------
// 1) fold: Wa (fp32), combined bias, qkv weights in B-frag order (f16)
// ---------------------------------------------------------------------------
__global__ void fold_k(const float* __restrict__ dwq, const float* __restrict__ pwq,
                       const float* __restrict__ bq,
                       const float* __restrict__ dwk, const float* __restrict__ pwk,
                       const float* __restrict__ bk,
                       const float* __restrict__ dwv, const float* __restrict__ pwv,
                       const float* __restrict__ bv,
                       const float* __restrict__ dwa, const float* __restrict__ pwa) {
    const int idx = blockIdx.x * 256 + threadIdx.x;   // 0..24575
    if (idx < 16384) {
        const int cr = idx >> 8;
        g_Wa[idx] = dwa[cr] * pwa[idx];
    }
    if (idx < 192)
        g_b192[idx] = (idx < 64) ? bq[idx] : (idx < 128 ? bk[idx - 64] : bv[idx - 128]);

    const int nn = idx >> 7;       // output unit 0..191
    const int p  = idx & 127;      // c-pair 0..127
    const int c0 = 2 * p, c1 = 2 * p + 1;
    float w0, w1;
    if (nn < 64)       { w0 = dwq[c0] * pwq[c0 * 64 + nn];        w1 = dwq[c1] * pwq[c1 * 64 + nn]; }
    else if (nn < 128) { const int m = nn - 64;  w0 = dwk[c0] * pwk[c0 * 64 + m]; w1 = dwk[c1] * pwk[c1 * 64 + m]; }
    else               { const int m = nn - 128; w0 = dwv[c0] * pwv[c0 * 64 + m]; w1 = dwv[c1] * pwv[c1 * 64 + m]; }
    const int h = nn / 96, nl = nn % 96, nt = nl >> 3, r = nl & 7;
    const int ks = p >> 3, rem = p & 7, q = rem & 3, slot = rem >> 2;
    g_Wfrag[(((h * 12 + nt) * 16 + ks) * 32 + r * 4 + q) * 2 + slot] = packf16(w0, w1);
}

// ---------------------------------------------------------------------------
// 2) QKV projection via mma.sync, f16 inputs / f32 acc (structure proven R6)
// ---------------------------------------------------------------------------
__global__ __launch_bounds__(256) void proj_k(const float* __restrict__ X) {
    __shared__ uint32_t sW[12288];   // 48 KB
    const int tid = threadIdx.x, lane = tid & 31, w = tid >> 5;
    const int r = lane >> 2, q = lane & 3;
    const int m0 = blockIdx.x * 128, h = blockIdx.y;

    const uint32_t swb = s2u(sW);
    const uint32_t* Wsrc = g_Wfrag + h * 12288;
    for (int t = tid; t < 3072; t += 256) cpasync16(swb + t * 16, Wsrc + t * 4);
    cpcommit(); cpwait<0>(); __syncthreads();

    float acc[12][4];
#pragma unroll
    for (int nt = 0; nt < 12; nt++) {
        const int n0 = h * 96 + nt * 8 + 2 * q;
        const float b0 = g_b192[n0], b1 = g_b192[n0 + 1];
        acc[nt][0] = b0; acc[nt][1] = b1; acc[nt][2] = b0; acc[nt][3] = b1;
    }

    const int mA = m0 + 16 * w + r;
    const float2* X2 = (const float2*)X;
    const uint2* sW2 = (const uint2*)sW;
#pragma unroll 4
    for (int ks = 0; ks < 16; ks++) {
        const float2 u0 = X2[(size_t)mA * 128 + ks * 8 + q];
        const float2 u1 = X2[(size_t)(mA + 8) * 128 + ks * 8 + q];
        const float2 u2 = X2[(size_t)mA * 128 + ks * 8 + q + 4];
        const float2 u3 = X2[(size_t)(mA + 8) * 128 + ks * 8 + q + 4];
        const uint32_t a0 = packf16(u0.x, u0.y);
        const uint32_t a1 = packf16(u1.x, u1.y);
        const uint32_t a2 = packf16(u2.x, u2.y);
        const uint32_t a3 = packf16(u3.x, u3.y);
#pragma unroll
        for (int nt = 0; nt < 12; nt++) {
            const uint2 b = sW2[(nt * 16 + ks) * 32 + lane];
            mma16816(acc[nt][0], acc[nt][1], acc[nt][2], acc[nt][3], a0, a1, a2, a3, b.x, b.y);
        }
    }

    uint32_t* Qw = (uint32_t*)g_Qh;
    uint32_t* Kw = (uint32_t*)g_Kh;
    const int nb = mA >> 12, ii = mA & 4095;
#pragma unroll
    for (int nt = 0; nt < 12; nt++) {
        const int n0 = h * 96 + nt * 8 + 2 * q;
        if (n0 < 64) {
            Qw[(size_t)mA * 32 + (n0 >> 1)]       = packf16(acc[nt][0], acc[nt][1]);
            Qw[(size_t)(mA + 8) * 32 + (n0 >> 1)] = packf16(acc[nt][2], acc[nt][3]);
        } else if (n0 < 128) {
            const int k0 = n0 - 64;
            Kw[(size_t)mA * 32 + (k0 >> 1)]       = packf16(acc[nt][0], acc[nt][1]);
            Kw[(size_t)(mA + 8) * 32 + (k0 >> 1)] = packf16(acc[nt][2], acc[nt][3]);
        } else {
            const int c = n0 - 128;
            g_Vth[((size_t)nb * 64 + c) * HW + ii]          = __float2half(acc[nt][0]);
            g_Vth[((size_t)nb * 64 + c + 1) * HW + ii]      = __float2half(acc[nt][1]);
            g_Vth[((size_t)nb * 64 + c) * HW + ii + 8]      = __float2half(acc[nt][2]);
            g_Vth[((size_t)nb * 64 + c + 1) * HW + ii + 8]  = __float2half(acc[nt][3]);
        }
    }
}

// ---------------------------------------------------------------------------
// 3) Pass A: rowsum partials over a j-quarter. 32 i-rows/warp, f16-acc MMA.
// ---------------------------------------------------------------------------
__global__ __launch_bounds__(128, 4) void rowsum_k() {
    __shared__ uint32_t sQ[2][128 * 36];
    const int tid = threadIdx.x, lane = tid & 31, w = tid >> 5;
    const int r = lane >> 2, q = lane & 3;
    const int i0 = blockIdx.x * 128, jq = blockIdx.y, n = blockIdx.z;

    uint32_t a[2][4][4];
    const uint32_t* Kg = (const uint32_t*)g_Kh + (size_t)n * HW * 32;
#pragma unroll
    for (int s = 0; s < 2; s++)
#pragma unroll
        for (int ks = 0; ks < 4; ks++) {
            const uint32_t* kr = Kg + (size_t)(i0 + 32 * w + 16 * s + r) * 32 + ks * 8 + q;
            a[s][ks][0] = kr[0]; a[s][ks][1] = kr[256]; a[s][ks][2] = kr[4]; a[s][ks][3] = kr[260];
        }
    const uint32_t* Qg = (const uint32_t*)g_Qh + ((size_t)n * HW + jq * 1024) * 32;
    const uint32_t sqb0 = s2u(sQ[0]), sqb1 = s2u(sQ[1]);
    const uint32_t loff = (lane & 7) * 144 + (lane >> 3) * 16;

    auto issue = [&](int ch, uint32_t base) {
#pragma unroll
        for (int t = tid; t < 1024; t += 128) {
            const int row = t >> 3, c4 = (t & 7) * 4;
            cpasync16(base + row * 144 + c4 * 4, Qg + (size_t)(ch * 128 + row) * 32 + c4);
        }
    };
    issue(0, sqb0); cpcommit();

    float sA[2] = {0.f, 0.f}, sB[2] = {0.f, 0.f};
    for (int ch = 0; ch < 8; ch++) {
        if (ch < 7) { issue(ch + 1, (ch & 1) ? sqb0 : sqb1); cpcommit(); cpwait<1>(); }
        else cpwait<0>();
        __syncthreads();
        const uint32_t base = (ch & 1) ? sqb1 : sqb0;
#pragma unroll 4
        for (int nt = 0; nt < 16; nt++) {
            uint32_t b00, b10, b01, b11, b02, b12, b03, b13;
            ldsm_x4(b00, b10, b01, b11, base + nt * 1152 + loff);
            ldsm_x4(b02, b12, b03, b13, base + nt * 1152 + 64 + loff);
#pragma unroll
            for (int s = 0; s < 2; s++) {
                uint32_t d0 = 0u, d1 = 0u;
                mma16816h(d0, d1, a[s][0][0], a[s][0][1], a[s][0][2], a[s][0][3], b00, b10);
                mma16816h(d0, d1, a[s][1][0], a[s][1][1], a[s][1][2], a[s][1][3], b01, b11);
                mma16816h(d0, d1, a[s][2][0], a[s][2][1], a[s][2][2], a[s][2][3], b02, b12);
                mma16816h(d0, d1, a[s][3][0], a[s][3][1], a[s][3][2], a[s][3][3], b03, b13);
                const float2 f0 = unpackh2(d0), f1 = unpackh2(d1);
                sA[s] += __expf(f0.x) + __expf(f0.y);
                sB[s] += __expf(f1.x) + __expf(f1.y);
            }
        }
        __syncthreads();
    }
#pragma unroll
    for (int s = 0; s < 2; s++) {
        float va = sA[s], vb = sB[s];
        va += __shfl_xor_sync(0xffffffffu, va, 1);
        va += __shfl_xor_sync(0xffffffffu, va, 2);
        vb += __shfl_xor_sync(0xffffffffu, vb, 1);
        vb += __shfl_xor_sync(0xffffffffu, vb, 2);
        if (q == 0) {
            g_part[jq][n * HW + i0 + 32 * w + 16 * s + r]     = va;
            g_part[jq][n * HW + i0 + 32 * w + 16 * s + r + 8] = vb;
        }
    }
}

// ---------------------------------------------------------------------------
// 4) Pass B over an i-quarter. 32 j-rows/warp, f16-acc MMA1+MMA2 (2x rate).
//    MMA1 f16 D-regs are already the packed (col,col+1) pairs for P'.
// ---------------------------------------------------------------------------
__global__ __launch_bounds__(128, 4) void attn_k() {
    __shared__ uint32_t sK[2][64 * 36];
    __shared__ uint32_t sVt[2][64 * 36];
    __shared__ float sInvAll[1024];
    const int tid = threadIdx.x, lane = tid & 31, w = tid >> 5;
    const int r = lane >> 2, q = lane & 3;
    const int j0 = blockIdx.x * 128, ih = blockIdx.y, n = blockIdx.z;

    for (int t = tid; t < 1024; t += 128) {
        const int gi = n * HW + ih * 1024 + t;
        sInvAll[t] = __frcp_rn(g_part[0][gi] + g_part[1][gi] + g_part[2][gi] + g_part[3][gi]);
    }

    uint32_t aq[2][4][4];
    const uint32_t* Qg = (const uint32_t*)g_Qh + (size_t)n * HW * 32;
#pragma unroll
    for (int s = 0; s < 2; s++)
#pragma unroll
        for (int ks = 0; ks < 4; ks++) {
            const uint32_t* qr = Qg + (size_t)(j0 + 32 * w + 16 * s + r) * 32 + ks * 8 + q;
            aq[s][ks][0] = qr[0]; aq[s][ks][1] = qr[256]; aq[s][ks][2] = qr[4]; aq[s][ks][3] = qr[260];
        }
    const uint32_t* Kg = (const uint32_t*)g_Kh + (size_t)n * HW * 32;
    const uint32_t* Vg = (const uint32_t*)g_Vth + (size_t)n * CR * (HW / 2);

    const uint32_t skb[2] = {s2u(sK[0]),  s2u(sK[1])};
    const uint32_t svb[2] = {s2u(sVt[0]), s2u(sVt[1])};
    const uint32_t loff1 = (lane & 7) * 144 + (lane >> 3) * 16;
    const uint32_t loff2 = (lane & 7) * 144 + ((lane >> 3) & 1) * 16 + (lane >> 4) * 1152;

    auto issue = [&](int ch, int buf) {
        const int i0 = ih * 1024 + ch * 64;
#pragma unroll
        for (int t = tid; t < 512; t += 128) {
            const int row = t >> 3, c4 = (t & 7) * 4;
            cpasync16(skb[buf] + row * 144 + c4 * 4, Kg + (size_t)(i0 + row) * 32 + c4);
            cpasync16(svb[buf] + row * 144 + c4 * 4, Vg + (size_t)row * 2048 + (i0 >> 1) + c4);
        }
    };

    uint32_t acc[2][8][2];
#pragma unroll
    for (int s = 0; s < 2; s++)
#pragma unroll
        for (int ct = 0; ct < 8; ct++)
            acc[s][ct][0] = acc[s][ct][1] = 0u;

    issue(0, 0); cpcommit();
    for (int ch = 0; ch < 16; ch++) {
        if (ch < 15) { issue(ch + 1, (ch + 1) & 1); cpcommit(); cpwait<1>(); }
        else cpwait<0>();
        __syncthreads();
        const int buf = ch & 1;
        const uint32_t kb = skb[buf], vb = svb[buf];
        const float* iv = sInvAll + ch * 64;

#pragma unroll
        for (int ks2 = 0; ks2 < 4; ks2++) {
            uint32_t ap[2][4];
#pragma unroll
            for (int half = 0; half < 2; half++) {
                const int nt = 2 * ks2 + half;
                uint32_t b00, b10, b01, b11, b02, b12, b03, b13;
                ldsm_x4(b00, b10, b01, b11, kb + nt * 1152 + loff1);
                ldsm_x4(b02, b12, b03, b13, kb + nt * 1152 + 64 + loff1);
                const float i0v = iv[nt * 8 + 2 * q];
                const float i1v = iv[nt * 8 + 2 * q + 1];
#pragma unroll
                for (int s = 0; s < 2; s++) {
                    uint32_t d0 = 0u, d1 = 0u;
                    mma16816h(d0, d1, aq[s][0][0], aq[s][0][1], aq[s][0][2], aq[s][0][3], b00, b10);
                    mma16816h(d0, d1, aq[s][1][0], aq[s][1][1], aq[s][1][2], aq[s][1][3], b01, b11);
                    mma16816h(d0, d1, aq[s][2][0], aq[s][2][1], aq[s][2][2], aq[s][2][3], b02, b12);
                    mma16816h(d0, d1, aq[s][3][0], aq[s][3][1], aq[s][3][2], aq[s][3][3], b03, b13);
                    const float2 f0 = unpackh2(d0), f1 = unpackh2(d1);
                    ap[s][half]     = packf16(__expf(f0.x) * i0v, __expf(f0.y) * i1v);
                    ap[s][2 + half] = packf16(__expf(f1.x) * i0v, __expf(f1.y) * i1v);
                }
            }
#pragma unroll
            for (int ctp = 0; ctp < 4; ctp++) {
                uint32_t v0, v1, v2, v3;
                ldsm_x4(v0, v1, v2, v3, vb + ctp * 2304 + ks2 * 32 + loff2);
#pragma unroll
                for (int s = 0; s < 2; s++) {
                    mma16816h(acc[s][2 * ctp][0], acc[s][2 * ctp][1],
                              ap[s][0], ap[s][2], ap[s][1], ap[s][3], v0, v1);
                    mma16816h(acc[s][2 * ctp + 1][0], acc[s][2 * ctp + 1][1],
                              ap[s][0], ap[s][2], ap[s][1], ap[s][3], v2, v3);
                }
            }
        }
        __syncthreads();
    }

    float* A = g_attp[ih] + (size_t)n * CR * HW;
#pragma unroll
    for (int s = 0; s < 2; s++) {
        const int jrow = j0 + 32 * w + 16 * s + r;
#pragma unroll
        for (int ct = 0; ct < 8; ct++) {
            const int c = ct * 8 + 2 * q;
            const float2 lo = unpackh2(acc[s][ct][0]);   // rows r:   (c, c+1)
            const float2 hi = unpackh2(acc[s][ct][1]);   // rows r+8: (c, c+1)
            A[(size_t)c * HW + jrow]           = lo.x;
            A[(size_t)(c + 1) * HW + jrow]     = lo.y;
            A[(size_t)c * HW + jrow + 8]       = hi.x;
            A[(size_t)(c + 1) * HW + jrow + 8] = hi.y;
        }
    }
}

// ---------------------------------------------------------------------------
// 5) Final (proven R7): block per (n,w); Wa column in registers.
// ---------------------------------------------------------------------------
__global__ __launch_bounds__(256) void final_k(const float* __restrict__ G,
                                               const float* __restrict__ ba,
                                               float* __restrict__ out) {
    __shared__ float sa[64][68];
    const int b = blockIdx.x;
    const int n = b >> 6, w = b & 63;
    const int tid = threadIdx.x;

    for (int idx = tid; idx < 4096; idx += 256) {
        const int c = idx >> 6, cr = idx & 63;
        const size_t base = ((size_t)n * CR + c) * HW + w * 64 + cr;
        sa[c][cr] = g_attp[0][base] + g_attp[1][base] + g_attp[2][base] + g_attp[3][base];
    }
    __syncthreads();

    float wa[64];
#pragma unroll
    for (int cr = 0; cr < 64; cr++) wa[cr] = g_Wa[cr * CIN + tid];
    const float vba = ba[tid];

    size_t gidx = ((size_t)n * HW + w) * CIN + tid;
    for (int h = 0; h < 64; h++) {
        float acc = vba;
        const float4* row = (const float4*)sa[h];
#pragma unroll
        for (int k = 0; k < 16; k++) {
            const float4 v = row[k];
            acc = fmaf(v.x, wa[4 * k],     acc);
            acc = fmaf(v.y, wa[4 * k + 1], acc);
            acc = fmaf(v.z, wa[4 * k + 2], acc);
            acc = fmaf(v.w, wa[4 * k + 3], acc);
        }
        const float g = G[gidx];
        out[gidx] = fmaf(g, acc, g);
        gidx += (size_t)64 * CIN;
    }
}

// ---------------------------------------------------------------------------
extern "C" void kernel_launch(void* const* d_in, const int* in_sizes, int n_in,
                              void* d_out, int out_size) {
    const float* X   = (const float*)d_in[0];
    const float* G   = (const float*)d_in[1];
    const float* dwq = (const float*)d_in[2];
    const float* pwq = (const float*)d_in[3];
    const float* bq  = (const float*)d_in[4];
    const float* dwk = (const float*)d_in[5];
    const float* pwk = (const float*)d_in[6];
    const float* bk  = (const float*)d_in[7];
    const float* dwv = (const float*)d_in[8];
    const float* pwv = (const float*)d_in[9];
    const float* bv  = (const float*)d_in[10];
    const float* dwa = (const float*)d_in[11];
    const float* pwa = (const float*)d_in[12];
    const float* ba  = (const float*)d_in[13];
    float* out = (float*)d_out;

    const int N = in_sizes[0] / (HW * CIN);   // 4

    fold_k<<<96, 256>>>(dwq, pwq, bq, dwk, pwk, bk, dwv, pwv, bv, dwa, pwa);
    proj_k<<<dim3((N * HW) / 128, 2), 256>>>(X);
    rowsum_k<<<dim3(HW / 128, 4, N), 128>>>();
    attn_k<<<dim3(HW / 128, 4, N), 128>>>();
    final_k<<<N * 64, 256>>>(G, ba, out);
}

// round 10
// speedup vs baseline: 7.9001x; 1.1651x over previous
#include <cuda_runtime.h>
#include <cuda_fp16.h>
#include <stdint.h>

// Shapes fixed by the problem: N=4, H=W=64, C_in=256, C_red=64
constexpr int HW   = 4096;
constexpr int CIN  = 256;
constexpr int CR   = 64;
constexpr int MAXN = 4;
constexpr float LOG2E = 1.4426950408889634f;

// ---------------- device scratch (allocation-free) ----------------
__device__ float g_Wa[CR * CIN];                          // fp32 [cr][cout], pre-scaled by 1/64
__device__ uint32_t g_Wfrag[2 * 12288];                   // qkv weights in B-fragment order (f16x2)
__device__ float g_b192[192];
__device__ __half g_Qh[(size_t)MAXN * HW * CR];           // [n*HW + j][c]
__device__ __half g_Kh[(size_t)MAXN * HW * CR];           // [n*HW + i][c], pre-scaled by log2e
__device__ __half g_Vth[(size_t)MAXN * CR * HW];          // [n][c][i] -> scaled to V''=V*64*inv_i
__device__ float g_part[4][MAXN * HW];                    // rowsum partials (j-quarters)
__device__ float g_attp[4][(size_t)MAXN * CR * HW];       // att partials [ih][n][c][j] (64x att)

// ---------------- helpers ----------------
__device__ __forceinline__ uint32_t s2u(const void* p) {
    return (uint32_t)__cvta_generic_to_shared(p);
}
__device__ __forceinline__ void mma16816(float& c0, float& c1, float& c2, float& c3,
                                         uint32_t a0, uint32_t a1, uint32_t a2, uint32_t a3,
                                         uint32_t b0, uint32_t b1) {
    asm volatile("mma.sync.aligned.m16n8k16.row.col.f32.f16.f16.f32 "
                 "{%0,%1,%2,%3}, {%4,%5,%6,%7}, {%8,%9}, {%0,%1,%2,%3};"
                 : "+f"(c0), "+f"(c1), "+f"(c2), "+f"(c3)
                 : "r"(a0), "r"(a1), "r"(a2), "r"(a3), "r"(b0), "r"(b1));
}
__device__ __forceinline__ void mma16816h(uint32_t& d0, uint32_t& d1,
                                          uint32_t a0, uint32_t a1, uint32_t a2, uint32_t a3,
                                          uint32_t b0, uint32_t b1) {
    asm volatile("mma.sync.aligned.m16n8k16.row.col.f16.f16.f16.f16 "
                 "{%0,%1}, {%2,%3,%4,%5}, {%6,%7}, {%0,%1};"
                 : "+r"(d0), "+r"(d1)
                 : "r"(a0), "r"(a1), "r"(a2), "r"(a3), "r"(b0), "r"(b1));
}
__device__ __forceinline__ uint32_t packf16(float lo, float hi) {
    uint32_t d;
    asm("cvt.rn.f16x2.f32 %0, %1, %2;" : "=r"(d) : "f"(hi), "f"(lo));
    return d;
}
__device__ __forceinline__ float2 unpackh2(uint32_t u) {
    __half2 h = *reinterpret_cast<__half2*>(&u);
    return __half22float2(h);
}
__device__ __forceinline__ uint32_t ex2h2(uint32_t x) {
    uint32_t d;
    asm("ex2.approx.f16x2 %0, %1;" : "=r"(d) : "r"(x));
    return d;
}
__device__ __forceinline__ float fex2(float x) {
    float d;
    asm("ex2.approx.ftz.f32 %0, %1;" : "=f"(d) : "f"(x));
    return d;
}
__device__ __forceinline__ void cpasync16(uint32_t saddr, const void* g) {
    asm volatile("cp.async.ca.shared.global [%0], [%1], 16;" :: "r"(saddr), "l"(g));
}
__device__ __forceinline__ void cpcommit() { asm volatile("cp.async.commit_group;"); }
template<int N> __device__ __forceinline__ void cpwait() {
    asm volatile("cp.async.wait_group %0;" :: "n"(N));
}
__device__ __forceinline__ void ldsm_x4(uint32_t& r0, uint32_t& r1, uint32_t& r2, uint32_t& r3,
                                        uint32_t addr) {
    asm volatile("ldmatrix.sync.aligned.m8n8.x4.shared.b16 {%0,%1,%2,%3}, [%4];"
                 : "=r"(r0), "=r"(r1), "=r"(r2), "=r"(r3) : "r"(addr));
}

// ---------------------------------------------------------------------------
// 1) fold: Wa (fp32, /64), bias, qkv weights in B-frag order; K scaled log2e
// ---------------------------------------------------------------------------
__global__ void fold_k(const float* __restrict__ dwq, const float* __restrict__ pwq,
                       const float* __restrict__ bq,
                       const float* __restrict__ dwk, const float* __restrict__ pwk,
                       const float* __restrict__ bk,
                       const float* __restrict__ dwv, const float* __restrict__ pwv,
                       const float* __restrict__ bv,
                       const float* __restrict__ dwa, const float* __restrict__ pwa) {
    const int idx = blockIdx.x * 256 + threadIdx.x;   // 0..24575
    if (idx < 16384) {
        const int cr = idx >> 8;
        g_Wa[idx] = dwa[cr] * pwa[idx] * 0.015625f;   // 1/64 compensates V'' scale
    }
    if (idx < 192)
        g_b192[idx] = (idx < 64) ? bq[idx]
                    : (idx < 128 ? bk[idx - 64] * LOG2E : bv[idx - 128]);

    const int nn = idx >> 7;       // output unit 0..191
    const int p  = idx & 127;      // c-pair 0..127
    const int c0 = 2 * p, c1 = 2 * p + 1;
    float w0, w1;
    if (nn < 64)       { w0 = dwq[c0] * pwq[c0 * 64 + nn];        w1 = dwq[c1] * pwq[c1 * 64 + nn]; }
    else if (nn < 128) { const int m = nn - 64;
                         w0 = dwk[c0] * pwk[c0 * 64 + m] * LOG2E;
                         w1 = dwk[c1] * pwk[c1 * 64 + m] * LOG2E; }
    else               { const int m = nn - 128; w0 = dwv[c0] * pwv[c0 * 64 + m]; w1 = dwv[c1] * pwv[c1 * 64 + m]; }
    const int h = nn / 96, nl = nn % 96, nt = nl >> 3, r = nl & 7;
    const int ks = p >> 3, rem = p & 7, q = rem & 3, slot = rem >> 2;
    g_Wfrag[(((h * 12 + nt) * 16 + ks) * 32 + r * 4 + q) * 2 + slot] = packf16(w0, w1);
}

// ---------------------------------------------------------------------------
// 2) QKV projection via mma.sync (proven R6/R9)
// ---------------------------------------------------------------------------
__global__ __launch_bounds__(256) void proj_k(const float* __restrict__ X) {
    __shared__ uint32_t sW[12288];   // 48 KB
    const int tid = threadIdx.x, lane = tid & 31, w = tid >> 5;
    const int r = lane >> 2, q = lane & 3;
    const int m0 = blockIdx.x * 128, h = blockIdx.y;

    const uint32_t swb = s2u(sW);
    const uint32_t* Wsrc = g_Wfrag + h * 12288;
    for (int t = tid; t < 3072; t += 256) cpasync16(swb + t * 16, Wsrc + t * 4);
    cpcommit(); cpwait<0>(); __syncthreads();

    float acc[12][4];
#pragma unroll
    for (int nt = 0; nt < 12; nt++) {
        const int n0 = h * 96 + nt * 8 + 2 * q;
        const float b0 = g_b192[n0], b1 = g_b192[n0 + 1];
        acc[nt][0] = b0; acc[nt][1] = b1; acc[nt][2] = b0; acc[nt][3] = b1;
    }

    const int mA = m0 + 16 * w + r;
    const float2* X2 = (const float2*)X;
    const uint2* sW2 = (const uint2*)sW;
#pragma unroll 4
    for (int ks = 0; ks < 16; ks++) {
        const float2 u0 = X2[(size_t)mA * 128 + ks * 8 + q];
        const float2 u1 = X2[(size_t)(mA + 8) * 128 + ks * 8 + q];
        const float2 u2 = X2[(size_t)mA * 128 + ks * 8 + q + 4];
        const float2 u3 = X2[(size_t)(mA + 8) * 128 + ks * 8 + q + 4];
        const uint32_t a0 = packf16(u0.x, u0.y);
        const uint32_t a1 = packf16(u1.x, u1.y);
        const uint32_t a2 = packf16(u2.x, u2.y);
        const uint32_t a3 = packf16(u3.x, u3.y);
#pragma unroll
        for (int nt = 0; nt < 12; nt++) {
            const uint2 b = sW2[(nt * 16 + ks) * 32 + lane];
            mma16816(acc[nt][0], acc[nt][1], acc[nt][2], acc[nt][3], a0, a1, a2, a3, b.x, b.y);
        }
    }

    uint32_t* Qw = (uint32_t*)g_Qh;
    uint32_t* Kw = (uint32_t*)g_Kh;
    const int nb = mA >> 12, ii = mA & 4095;
#pragma unroll
    for (int nt = 0; nt < 12; nt++) {
        const int n0 = h * 96 + nt * 8 + 2 * q;
        if (n0 < 64) {
            Qw[(size_t)mA * 32 + (n0 >> 1)]       = packf16(acc[nt][0], acc[nt][1]);
            Qw[(size_t)(mA + 8) * 32 + (n0 >> 1)] = packf16(acc[nt][2], acc[nt][3]);
        } else if (n0 < 128) {
            const int k0 = n0 - 64;
            Kw[(size_t)mA * 32 + (k0 >> 1)]       = packf16(acc[nt][0], acc[nt][1]);
            Kw[(size_t)(mA + 8) * 32 + (k0 >> 1)] = packf16(acc[nt][2], acc[nt][3]);
        } else {
            const int c = n0 - 128;
            g_Vth[((size_t)nb * 64 + c) * HW + ii]          = __float2half(acc[nt][0]);
            g_Vth[((size_t)nb * 64 + c + 1) * HW + ii]      = __float2half(acc[nt][1]);
            g_Vth[((size_t)nb * 64 + c) * HW + ii + 8]      = __float2half(acc[nt][2]);
            g_Vth[((size_t)nb * 64 + c + 1) * HW + ii + 8]  = __float2half(acc[nt][3]);
        }
    }
}

// ---------------------------------------------------------------------------
// 3) Pass A: rowsum partials. S' = S*log2e (K pre-scaled) -> ex2.
// ---------------------------------------------------------------------------
__global__ __launch_bounds__(128, 4) void rowsum_k() {
    __shared__ uint32_t sQ[2][128 * 36];
    const int tid = threadIdx.x, lane = tid & 31, w = tid >> 5;
    const int r = lane >> 2, q = lane & 3;
    const int i0 = blockIdx.x * 128, jq = blockIdx.y, n = blockIdx.z;

    uint32_t a[2][4][4];
    const uint32_t* Kg = (const uint32_t*)g_Kh + (size_t)n * HW * 32;
#pragma unroll
    for (int s = 0; s < 2; s++)
#pragma unroll
        for (int ks = 0; ks < 4; ks++) {
            const uint32_t* kr = Kg + (size_t)(i0 + 32 * w + 16 * s + r) * 32 + ks * 8 + q;
            a[s][ks][0] = kr[0]; a[s][ks][1] = kr[256]; a[s][ks][2] = kr[4]; a[s][ks][3] = kr[260];
        }
    const uint32_t* Qg = (const uint32_t*)g_Qh + ((size_t)n * HW + jq * 1024) * 32;
    const uint32_t sqb0 = s2u(sQ[0]), sqb1 = s2u(sQ[1]);
    const uint32_t loff = (lane & 7) * 144 + (lane >> 3) * 16;

    auto issue = [&](int ch, uint32_t base) {
#pragma unroll
        for (int t = tid; t < 1024; t += 128) {
            const int row = t >> 3, c4 = (t & 7) * 4;
            cpasync16(base + row * 144 + c4 * 4, Qg + (size_t)(ch * 128 + row) * 32 + c4);
        }
    };
    issue(0, sqb0); cpcommit();

    float sA[2] = {0.f, 0.f}, sB[2] = {0.f, 0.f};
    for (int ch = 0; ch < 8; ch++) {
        if (ch < 7) { issue(ch + 1, (ch & 1) ? sqb0 : sqb1); cpcommit(); cpwait<1>(); }
        else cpwait<0>();
        __syncthreads();
        const uint32_t base = (ch & 1) ? sqb1 : sqb0;
#pragma unroll 4
        for (int nt = 0; nt < 16; nt++) {
            uint32_t b00, b10, b01, b11, b02, b12, b03, b13;
            ldsm_x4(b00, b10, b01, b11, base + nt * 1152 + loff);
            ldsm_x4(b02, b12, b03, b13, base + nt * 1152 + 64 + loff);
#pragma unroll
            for (int s = 0; s < 2; s++) {
                uint32_t d0 = 0u, d1 = 0u;
                mma16816h(d0, d1, a[s][0][0], a[s][0][1], a[s][0][2], a[s][0][3], b00, b10);
                mma16816h(d0, d1, a[s][1][0], a[s][1][1], a[s][1][2], a[s][1][3], b01, b11);
                mma16816h(d0, d1, a[s][2][0], a[s][2][1], a[s][2][2], a[s][2][3], b02, b12);
                mma16816h(d0, d1, a[s][3][0], a[s][3][1], a[s][3][2], a[s][3][3], b03, b13);
                const float2 f0 = unpackh2(d0), f1 = unpackh2(d1);
                sA[s] += fex2(f0.x) + fex2(f0.y);
                sB[s] += fex2(f1.x) + fex2(f1.y);
            }
        }
        __syncthreads();
    }
#pragma unroll
    for (int s = 0; s < 2; s++) {
        float va = sA[s], vb = sB[s];
        va += __shfl_xor_sync(0xffffffffu, va, 1);
        va += __shfl_xor_sync(0xffffffffu, va, 2);
        vb += __shfl_xor_sync(0xffffffffu, vb, 1);
        vb += __shfl_xor_sync(0xffffffffu, vb, 2);
        if (q == 0) {
            g_part[jq][n * HW + i0 + 32 * w + 16 * s + r]     = va;
            g_part[jq][n * HW + i0 + 32 * w + 16 * s + r + 8] = vb;
        }
    }
}

// ---------------------------------------------------------------------------
// 3b) scale V in place: V''[c,i] = V[c,i] * 64 / rowsum_i
// ---------------------------------------------------------------------------
__global__ void scalev_k() {
    const int idx = blockIdx.x * 256 + threadIdx.x;   // over half2 elements
    const int i2 = idx % (HW / 2);                    // half2 index along i
    const int nc = idx / (HW / 2);                    // n*64 + c
    const int n = nc >> 6;
    const int gi = n * HW + i2 * 2;
    const float inv0 = 64.0f / (g_part[0][gi] + g_part[1][gi] + g_part[2][gi] + g_part[3][gi]);
    const float inv1 = 64.0f / (g_part[0][gi + 1] + g_part[1][gi + 1] + g_part[2][gi + 1] + g_part[3][gi + 1]);
    __half2* V2 = (__half2*)g_Vth;
    const float2 v = __half22float2(V2[(size_t)nc * (HW / 2) + i2]);
    V2[(size_t)nc * (HW / 2) + i2] = __floats2half2_rn(v.x * inv0, v.y * inv1);
}

// ---------------------------------------------------------------------------
// 4) Pass B over an i-quarter. P' fragment = ex2.f16x2(MMA1 D-reg). No inv,
//    no packs: softmax is ONE instruction per fragment register.
// ---------------------------------------------------------------------------
__global__ __launch_bounds__(128, 4) void attn_k() {
    __shared__ uint32_t sK[2][64 * 36];
    __shared__ uint32_t sVt[2][64 * 36];
    const int tid = threadIdx.x, lane = tid & 31, w = tid >> 5;
    const int r = lane >> 2, q = lane & 3;
    const int j0 = blockIdx.x * 128, ih = blockIdx.y, n = blockIdx.z;

    uint32_t aq[2][4][4];
    const uint32_t* Qg = (const uint32_t*)g_Qh + (size_t)n * HW * 32;
#pragma unroll
    for (int s = 0; s < 2; s++)
#pragma unroll
        for (int ks = 0; ks < 4; ks++) {
            const uint32_t* qr = Qg + (size_t)(j0 + 32 * w + 16 * s + r) * 32 + ks * 8 + q;
            aq[s][ks][0] = qr[0]; aq[s][ks][1] = qr[256]; aq[s][ks][2] = qr[4]; aq[s][ks][3] = qr[260];
        }
    const uint32_t* Kg = (const uint32_t*)g_Kh + (size_t)n * HW * 32;
    const uint32_t* Vg = (const uint32_t*)g_Vth + (size_t)n * CR * (HW / 2);

    const uint32_t skb[2] = {s2u(sK[0]),  s2u(sK[1])};
    const uint32_t svb[2] = {s2u(sVt[0]), s2u(sVt[1])};
    const uint32_t loff1 = (lane & 7) * 144 + (lane >> 3) * 16;
    const uint32_t loff2 = (lane & 7) * 144 + ((lane >> 3) & 1) * 16 + (lane >> 4) * 1152;

    auto issue = [&](int ch, int buf) {
        const int i0 = ih * 1024 + ch * 64;
#pragma unroll
        for (int t = tid; t < 512; t += 128) {
            const int row = t >> 3, c4 = (t & 7) * 4;
            cpasync16(skb[buf] + row * 144 + c4 * 4, Kg + (size_t)(i0 + row) * 32 + c4);
            cpasync16(svb[buf] + row * 144 + c4 * 4, Vg + (size_t)row * 2048 + (i0 >> 1) + c4);
        }
    };

    uint32_t acc[2][8][2];
#pragma unroll
    for (int s = 0; s < 2; s++)
#pragma unroll
        for (int ct = 0; ct < 8; ct++)
            acc[s][ct][0] = acc[s][ct][1] = 0u;

    issue(0, 0); cpcommit();
    for (int ch = 0; ch < 16; ch++) {
        if (ch < 15) { issue(ch + 1, (ch + 1) & 1); cpcommit(); cpwait<1>(); }
        else cpwait<0>();
        __syncthreads();
        const int buf = ch & 1;
        const uint32_t kb = skb[buf], vb = svb[buf];

#pragma unroll
        for (int ks2 = 0; ks2 < 4; ks2++) {
            uint32_t ap[2][4];
#pragma unroll
            for (int half = 0; half < 2; half++) {
                const int nt = 2 * ks2 + half;
                uint32_t b00, b10, b01, b11, b02, b12, b03, b13;
                ldsm_x4(b00, b10, b01, b11, kb + nt * 1152 + loff1);
                ldsm_x4(b02, b12, b03, b13, kb + nt * 1152 + 64 + loff1);
#pragma unroll
                for (int s = 0; s < 2; s++) {
                    uint32_t d0 = 0u, d1 = 0u;
                    mma16816h(d0, d1, aq[s][0][0], aq[s][0][1], aq[s][0][2], aq[s][0][3], b00, b10);
                    mma16816h(d0, d1, aq[s][1][0], aq[s][1][1], aq[s][1][2], aq[s][1][3], b01, b11);
                    mma16816h(d0, d1, aq[s][2][0], aq[s][2][1], aq[s][2][2], aq[s][2][3], b02, b12);
                    mma16816h(d0, d1, aq[s][3][0], aq[s][3][1], aq[s][3][2], aq[s][3][3], b03, b13);
                    ap[s][half]     = ex2h2(d0);
                    ap[s][2 + half] = ex2h2(d1);
                }
            }
#pragma unroll
            for (int ctp = 0; ctp < 4; ctp++) {
                uint32_t v0, v1, v2, v3;
                ldsm_x4(v0, v1, v2, v3, vb + ctp * 2304 + ks2 * 32 + loff2);
#pragma unroll
                for (int s = 0; s < 2; s++) {
                    mma16816h(acc[s][2 * ctp][0], acc[s][2 * ctp][1],
                              ap[s][0], ap[s][2], ap[s][1], ap[s][3], v0, v1);
                    mma16816h(acc[s][2 * ctp + 1][0], acc[s][2 * ctp + 1][1],
                              ap[s][0], ap[s][2], ap[s][1], ap[s][3], v2, v3);
                }
            }
        }
        __syncthreads();
    }

    float* A = g_attp[ih] + (size_t)n * CR * HW;
#pragma unroll
    for (int s = 0; s < 2; s++) {
        const int jrow = j0 + 32 * w + 16 * s + r;
#pragma unroll
        for (int ct = 0; ct < 8; ct++) {
            const int c = ct * 8 + 2 * q;
            const float2 lo = unpackh2(acc[s][ct][0]);
            const float2 hi = unpackh2(acc[s][ct][1]);
            A[(size_t)c * HW + jrow]           = lo.x;
            A[(size_t)(c + 1) * HW + jrow]     = lo.y;
            A[(size_t)c * HW + jrow + 8]       = hi.x;
            A[(size_t)(c + 1) * HW + jrow + 8] = hi.y;
        }
    }
}

// ---------------------------------------------------------------------------
// 5) Final (proven R7): Wa pre-scaled by 1/64 compensates V'' scaling.
// ---------------------------------------------------------------------------
__global__ __launch_bounds__(256) void final_k(const float* __restrict__ G,
                                               const float* __restrict__ ba,
                                               float* __restrict__ out) {
    __shared__ float sa[64][68];
    const int b = blockIdx.x;
    const int n = b >> 6, w = b & 63;
    const int tid = threadIdx.x;

    for (int idx = tid; idx < 4096; idx += 256) {
        const int c = idx >> 6, cr = idx & 63;
        const size_t base = ((size_t)n * CR + c) * HW + w * 64 + cr;
        sa[c][cr] = g_attp[0][base] + g_attp[1][base] + g_attp[2][base] + g_attp[3][base];
    }
    __syncthreads();

    float wa[64];
#pragma unroll
    for (int cr = 0; cr < 64; cr++) wa[cr] = g_Wa[cr * CIN + tid];
    const float vba = ba[tid];

    size_t gidx = ((size_t)n * HW + w) * CIN + tid;
    for (int h = 0; h < 64; h++) {
        float acc = vba;
        const float4* row = (const float4*)sa[h];
#pragma unroll
        for (int k = 0; k < 16; k++) {
            const float4 v = row[k];
            acc = fmaf(v.x, wa[4 * k],     acc);
            acc = fmaf(v.y, wa[4 * k + 1], acc);
            acc = fmaf(v.z, wa[4 * k + 2], acc);
            acc = fmaf(v.w, wa[4 * k + 3], acc);
        }
        const float g = G[gidx];
        out[gidx] = fmaf(g, acc, g);
        gidx += (size_t)64 * CIN;
    }
}

// ---------------------------------------------------------------------------
extern "C" void kernel_launch(void* const* d_in, const int* in_sizes, int n_in,
                              void* d_out, int out_size) {
    const float* X   = (const float*)d_in[0];
    const float* G   = (const float*)d_in[1];
    const float* dwq = (const float*)d_in[2];
    const float* pwq = (const float*)d_in[3];
    const float* bq  = (const float*)d_in[4];
    const float* dwk = (const float*)d_in[5];
    const float* pwk = (const float*)d_in[6];
    const float* bk  = (const float*)d_in[7];
    const float* dwv = (const float*)d_in[8];
    const float* pwv = (const float*)d_in[9];
    const float* bv  = (const float*)d_in[10];
    const float* dwa = (const float*)d_in[11];
    const float* pwa = (const float*)d_in[12];
    const float* ba  = (const float*)d_in[13];
    float* out = (float*)d_out;

    const int N = in_sizes[0] / (HW * CIN);   // 4

    fold_k<<<96, 256>>>(dwq, pwq, bq, dwk, pwk, bk, dwv, pwv, bv, dwa, pwa);
    proj_k<<<dim3((N * HW) / 128, 2), 256>>>(X);
    rowsum_k<<<dim3(HW / 128, 4, N), 128>>>();
    scalev_k<<<(N * CR * HW / 2) / 256, 256>>>();
    attn_k<<<dim3(HW / 128, 4, N), 128>>>();
    final_k<<<N * 64, 256>>>(G, ba, out);
}